// round 7
// baseline (speedup 1.0000x reference)
#include <cuda_runtime.h>
#include <cuda_bf16.h>
#include <cstdint>

#define IC1 10
#define OC1 64
#define OC2 128
#define NB  64

__device__ int   g_cnt[NB][OC1][9];   // S, Rf, Rl, Cf, Cl, q_tl, q_tr, q_bl, q_br
__device__ float g_s2[NB][OC2];
__device__ float g_inv1[OC1],  g_beta1[OC1];
__device__ float g_inv2[OC2],  g_beta2[OC2];
// weights, k-major transposed + split: Wt[k=tap*16+ic][oc], rows padded to 72
__device__ __align__(16) uint16_t g_Wth[144 * 72];
__device__ __align__(16) uint16_t g_Wtl[144 * 72];

// ---------------- warp-mma helpers (portable sm_80+ path) ----------------
__device__ __forceinline__ uint32_t smem_u32(const void* p) {
    uint32_t a;
    asm("{ .reg .u64 t; cvta.to.shared.u64 t, %1; cvt.u32.u64 %0, t; }" : "=r"(a) : "l"(p));
    return a;
}
__device__ __forceinline__ void ldsm_x4(uint32_t& r0, uint32_t& r1, uint32_t& r2, uint32_t& r3, uint32_t a) {
    asm volatile("ldmatrix.sync.aligned.m8n8.x4.shared.b16 {%0,%1,%2,%3}, [%4];"
                 : "=r"(r0), "=r"(r1), "=r"(r2), "=r"(r3) : "r"(a));
}
__device__ __forceinline__ void ldsm_x2_t(uint32_t& r0, uint32_t& r1, uint32_t a) {
    asm volatile("ldmatrix.sync.aligned.m8n8.x2.trans.shared.b16 {%0,%1}, [%2];"
                 : "=r"(r0), "=r"(r1) : "r"(a));
}
__device__ __forceinline__ void mma16816(float& c0, float& c1, float& c2, float& c3,
                                         uint32_t a0, uint32_t a1, uint32_t a2, uint32_t a3,
                                         uint32_t b0, uint32_t b1) {
    asm volatile("mma.sync.aligned.m16n8k16.row.col.f32.bf16.bf16.f32 "
                 "{%0,%1,%2,%3},{%4,%5,%6,%7},{%8,%9},{%0,%1,%2,%3};"
                 : "+f"(c0), "+f"(c1), "+f"(c2), "+f"(c3)
                 : "r"(a0), "r"(a1), "r"(a2), "r"(a3), "r"(b0), "r"(b1));
}

// ---------------- smem layout (bytes) ----------------
#define SM_BN   0        // float[128]
#define SM_RED  512      // int[256]
#define SM_SPK  1536     // uchar[4096]
#define SM_SHI  5632     // bf16[6*66*16] = 12672 B
#define SM_SLO  18304
#define SM_AHI  30976    // 256 rows x 48 B
#define SM_ALO  43264
#define SM_BHI  55552    // 144 rows x 144 B
#define SM_BLO  76288
#define SMEM_BYTES 97024

// ---------------------------------------------------------------------------
// prep: zero counters, fold BN, build split-bf16 transposed weight images
// ---------------------------------------------------------------------------
__global__ void prep_kernel(const float* __restrict__ w1,
                            const float* __restrict__ g1, const float* __restrict__ b1,
                            const float* __restrict__ m1, const float* __restrict__ v1,
                            const float* __restrict__ g2, const float* __restrict__ b2,
                            const float* __restrict__ m2, const float* __restrict__ v2) {
    int gid = blockIdx.x * blockDim.x + threadIdx.x;
    int* c = &g_cnt[0][0][0];
    for (int i = gid; i < NB * OC1 * 9; i += gridDim.x * blockDim.x) c[i] = 0;
    if (blockIdx.x == 0) {
        int t = threadIdx.x;
        if (t < OC1) {
            float inv = g1[t] / sqrtf(v1[t] + 1e-5f);
            g_inv1[t] = inv;
            g_beta1[t] = b1[t] - m1[t] * inv;
        }
        if (t < OC2) {
            float inv = g2[t] / sqrtf(v2[t] + 1e-5f);
            g_inv2[t] = inv;
            g_beta2[t] = b2[t] - m2[t] * inv;
        }
    }
    if (gid < 144 * 72) {
        int k = gid / 72, oc = gid % 72;
        int j = k >> 4, ic = k & 15;
        float v = (ic < IC1 && oc < OC1) ? __ldg(&w1[oc * 90 + ic * 9 + j]) : 0.f;
        __nv_bfloat16 h = __float2bfloat16(v);
        __nv_bfloat16 lo = __float2bfloat16(v - __bfloat162float(h));
        g_Wth[gid] = __bfloat16_as_ushort(h);
        g_Wtl[gid] = __bfloat16_as_ushort(lo);
    }
}

// ---------------------------------------------------------------------------
// stage T: conv1 as 3-pass split-bf16 mma.sync GEMM + BN + maxpool2 + spike
// grid (4, 64, 64): x = 64-col strip, y = 4 conv rows, z = n. 256 threads.
// ---------------------------------------------------------------------------
__global__ __launch_bounds__(256, 2) void stageT_kernel(const float* __restrict__ x0,
                                                        const float* __restrict__ x1) {
    extern __shared__ char smem[];
    const uint32_t sb = smem_u32(smem);
    float*         sBN  = (float*)(smem + SM_BN);
    int*           sred = (int*)(smem + SM_RED);
    unsigned char* spk  = (unsigned char*)(smem + SM_SPK);

    const int tid = threadIdx.x, w = tid >> 5, l = tid & 31;
    const int bx = blockIdx.x, by = blockIdx.y, n = blockIdx.z;
    const float* __restrict__ x = (n < 32) ? x0 : x1;
    const int b = n & 31;

    // BN + weight tiles into smem
    if (tid < 128) sBN[tid] = (tid < 64) ? __ldg(&g_inv1[tid]) : __ldg(&g_beta1[tid - 64]);
    {
        const uint4* gh = (const uint4*)g_Wth;
        const uint4* gl = (const uint4*)g_Wtl;
        uint4* sh = (uint4*)(smem + SM_BHI);
        uint4* sl = (uint4*)(smem + SM_BLO);
        for (int i = tid; i < 1296; i += 256) { sh[i] = __ldg(&gh[i]); sl[i] = __ldg(&gl[i]); }
    }
    // zero staging (covers ic padding and image-edge halo)
    {
        uint4 z = make_uint4(0, 0, 0, 0);
        uint4* sh = (uint4*)(smem + SM_SHI);
        for (int i = tid; i < 1584; i += 256) sh[i] = z;   // covers SHI+SLO (contiguous 25344 B)
    }
    __syncthreads();

    // stage input rows 4by-1..4by+4, cols 64bx-1..64bx+64, ic-interleaved bf16 hi/lo
    {
        const int gy0 = 4 * by - 1, gx0 = 64 * bx - 1;
        uint16_t* sh = (uint16_t*)(smem + SM_SHI);
        uint16_t* sl = (uint16_t*)(smem + SM_SLO);
        for (int i = tid; i < 3960; i += 256) {
            int ic = i / 396, rem = i % 396, rw = rem / 66, cl = rem % 66;
            int gy = gy0 + rw, gx = gx0 + cl;
            if ((unsigned)gy < 256u && (unsigned)gx < 256u) {
                float v = __ldg(&x[((b * IC1 + ic) * 256 + gy) * 256 + gx]);
                __nv_bfloat16 h = __float2bfloat16(v);
                __nv_bfloat16 lo = __float2bfloat16(v - __bfloat162float(h));
                int off = (rw * 66 + cl) * 16 + ic;
                sh[off] = __bfloat16_as_ushort(h);
                sl[off] = __bfloat16_as_ushort(lo);
            }
        }
    }
    __syncthreads();

    // thread's A-row position
    const int rt = tid & 15, mtp = tid >> 4;
    const int v_ = rt >> 3, u_ = rt & 1, j_ = (rt & 7) >> 1;
    const int Q_ = 4 * mtp + j_;
    const int r_local = 2 * (Q_ >> 5) + u_;
    const int c_local = 2 * (Q_ & 31) + v_;

    // ldmatrix lane-address components
    const uint32_t arow = (uint32_t)((l & 7) + ((l >> 3) & 1) * 8);
    const uint32_t aoff = arow * 48u + (uint32_t)(l >> 4) * 16u;
    const uint32_t brow = (uint32_t)(l & 15);

    float acc[2][8][4];
#pragma unroll
    for (int a = 0; a < 2; ++a)
#pragma unroll
        for (int nt = 0; nt < 8; ++nt)
#pragma unroll
            for (int q = 0; q < 4; ++q) acc[a][nt][q] = 0.f;

#pragma unroll 1
    for (int s = 0; s < 9; ++s) {
        // build A tiles for tap s (pure 32B copies from ic-interleaved staging)
        {
            const int ky = s / 3, kx = s % 3;
            const uint32_t so = (uint32_t)(((r_local + ky) * 66 + (c_local + kx)) * 32);
            const uint4* sh = (const uint4*)(smem + SM_SHI + so);
            const uint4* sl = (const uint4*)(smem + SM_SLO + so);
            uint4* dh = (uint4*)(smem + SM_AHI + tid * 48);
            uint4* dl = (uint4*)(smem + SM_ALO + tid * 48);
            uint4 h0 = sh[0], h1 = sh[1];
            uint4 l0 = sl[0], l1 = sl[1];
            dh[0] = h0; dh[1] = h1;
            dl[0] = l0; dl[1] = l1;
        }
        __syncthreads();

        uint32_t Ah[2][4], Al[2][4];
#pragma unroll
        for (int m2 = 0; m2 < 2; ++m2) {
            const uint32_t base = (uint32_t)((2 * w + m2) * 16) * 48u + aoff;
            ldsm_x4(Ah[m2][0], Ah[m2][1], Ah[m2][2], Ah[m2][3], sb + SM_AHI + base);
            ldsm_x4(Al[m2][0], Al[m2][1], Al[m2][2], Al[m2][3], sb + SM_ALO + base);
        }
        const uint32_t bbase = ((uint32_t)s * 16u + brow) * 144u;
#pragma unroll
        for (int nt = 0; nt < 8; ++nt) {
            uint32_t bh0, bh1, bl0, bl1;
            ldsm_x2_t(bh0, bh1, sb + SM_BHI + bbase + (uint32_t)nt * 16u);
            ldsm_x2_t(bl0, bl1, sb + SM_BLO + bbase + (uint32_t)nt * 16u);
#pragma unroll
            for (int m2 = 0; m2 < 2; ++m2) {
                float* c = acc[m2][nt];
                mma16816(c[0], c[1], c[2], c[3], Ah[m2][0], Ah[m2][1], Ah[m2][2], Ah[m2][3], bh0, bh1);
                mma16816(c[0], c[1], c[2], c[3], Al[m2][0], Al[m2][1], Al[m2][2], Al[m2][3], bh0, bh1);
                mma16816(c[0], c[1], c[2], c[3], Ah[m2][0], Ah[m2][1], Ah[m2][2], Ah[m2][3], bl0, bl1);
            }
        }
        __syncthreads();
    }

    // epilogue: BN affine -> pool max (fmax + shfl) -> spike bits into spk[]
    {
        const int a_ = l >> 2;                 // fragment row 0..7
        const bool lead = (a_ & 1) == 0;
        const int jq = a_ >> 1;                // local quad j
        const int q0 = 2 * (l & 3);
#pragma unroll
        for (int m2 = 0; m2 < 2; ++m2) {
            const int mt = 2 * w + m2;
#pragma unroll
            for (int nt = 0; nt < 8; ++nt) {
                const int oc0 = nt * 8 + q0, oc1 = oc0 + 1;
                const float* c = acc[m2][nt];
                float z0 = fmaf(c[0], sBN[oc0], sBN[64 + oc0]);
                float z1 = fmaf(c[1], sBN[oc1], sBN[64 + oc1]);
                float z2 = fmaf(c[2], sBN[oc0], sBN[64 + oc0]);
                float z3 = fmaf(c[3], sBN[oc1], sBN[64 + oc1]);
                float m0 = fmaxf(z0, z2);
                float m1 = fmaxf(z1, z3);
                m0 = fmaxf(m0, __shfl_xor_sync(0xffffffffu, m0, 4));
                m1 = fmaxf(m1, __shfl_xor_sync(0xffffffffu, m1, 4));
                if (lead) {
                    const int Q = 4 * mt + jq;
                    spk[Q * 64 + oc0] = (m0 > 1.0f);
                    spk[Q * 64 + oc1] = (m1 > 1.0f);
                }
            }
        }
    }
    __syncthreads();

    // reduce spike map -> aggregates
    {
        const int oc = tid & 63, grp = tid >> 6;
        int s = 0;
#pragma unroll
        for (int q = 0; q < 16; ++q) s += spk[(grp * 16 + q) * 64 + oc];
        sred[grp * 64 + oc] = s;
    }
    __syncthreads();
    if (tid < 64) {
        const int oc = tid;
        int Sf = sred[oc] + sred[64 + oc];          // quads 0-31 (pooled row 2by)
        int Sl = sred[128 + oc] + sred[192 + oc];   // quads 32-63 (pooled row 2by+1)
        int S = Sf + Sl;
        if (S) atomicAdd(&g_cnt[n][oc][0], S);
        if (by == 0 && Sf)  atomicAdd(&g_cnt[n][oc][1], Sf);
        if (by == 63 && Sl) atomicAdd(&g_cnt[n][oc][2], Sl);
        if (bx == 0) {
            int Cf = spk[0 * 64 + oc] + spk[32 * 64 + oc];
            if (Cf) atomicAdd(&g_cnt[n][oc][3], Cf);
            if (by == 0 && spk[0 * 64 + oc])   g_cnt[n][oc][5] = 1;
            if (by == 63 && spk[32 * 64 + oc]) g_cnt[n][oc][7] = 1;
        }
        if (bx == 3) {
            int Cl = spk[31 * 64 + oc] + spk[63 * 64 + oc];
            if (Cl) atomicAdd(&g_cnt[n][oc][4], Cl);
            if (by == 0 && spk[31 * 64 + oc])  g_cnt[n][oc][6] = 1;
            if (by == 63 && spk[63 * 64 + oc]) g_cnt[n][oc][8] = 1;
        }
    }
}

// ---------------------------------------------------------------------------
// stage B: analytic conv2-mean via T aggregates, BN2, spike -> g_s2
// ---------------------------------------------------------------------------
__global__ __launch_bounds__(256) void stageB_kernel(const float* __restrict__ w2) {
    __shared__ __align__(16) float sT[OC1 * 9];
    const int n = blockIdx.x, tid = threadIdx.x;
    const int lane = tid & 31, warp = tid >> 5;
    if (tid < OC1) {
        const int* c = g_cnt[n][tid];
        int S = c[0], Rf = c[1], Rl = c[2], Cf = c[3], Cl = c[4];
        int Re[3] = {Rl, 0, Rf};
        int Ce[3] = {Cl, 0, Cf};
        int Q[9]  = {c[8], 0, c[7],  0, 0, 0,  c[6], 0, c[5]};
#pragma unroll
        for (int k = 0; k < 9; ++k)
            sT[tid * 9 + k] = (float)(S - Re[k / 3] - Ce[k % 3] + Q[k]);
    }
    __syncthreads();
#pragma unroll 1
    for (int i = 0; i < 16; ++i) {
        const int o = warp * 16 + i;
        const float* wr = w2 + o * 576;
        float acc = 0.f;
#pragma unroll
        for (int t = 0; t < 18; ++t) {
            int j = t * 32 + lane;
            acc = fmaf(__ldg(&wr[j]), sT[j], acc);
        }
#pragma unroll
        for (int s = 16; s; s >>= 1) acc += __shfl_xor_sync(0xffffffffu, acc, s);
        if (lane == 0) {
            float z = acc * (1.f / 16384.f);
            z = z * g_inv2[o] + g_beta2[o];
            g_s2[n][o] = (z > 1.f) ? 1.f : 0.f;
        }
    }
}

// ---------------------------------------------------------------------------
// stage C: feat = |s0 - s1|, fc1+relu, fc2  -> out (32,5)
// ---------------------------------------------------------------------------
__global__ __launch_bounds__(256) void stageC_kernel(const float* __restrict__ fc1w,
                                                     const float* __restrict__ fc1b,
                                                     const float* __restrict__ fc2w,
                                                     const float* __restrict__ fc2b,
                                                     float* __restrict__ out) {
    __shared__ float f[128];
    __shared__ float h[64];
    const int n = blockIdx.x, tid = threadIdx.x;
    const int lane = tid & 31, warp = tid >> 5;
    if (tid < 128) f[tid] = fabsf(g_s2[n][tid] - g_s2[n + 32][tid]);
    __syncthreads();
#pragma unroll 1
    for (int i = 0; i < 8; ++i) {
        const int k = warp * 8 + i;
        const float* wr = fc1w + k * 128;
        float acc = 0.f;
#pragma unroll
        for (int t = 0; t < 4; ++t) {
            int j = t * 32 + lane;
            acc = fmaf(__ldg(&wr[j]), f[j], acc);
        }
#pragma unroll
        for (int s = 16; s; s >>= 1) acc += __shfl_xor_sync(0xffffffffu, acc, s);
        if (lane == 0) h[k] = fmaxf(acc + fc1b[k], 0.f);
    }
    __syncthreads();
    if (warp == 0) {
#pragma unroll 1
        for (int c = 0; c < 5; ++c) {
            const float* wr = fc2w + c * 64;
            float acc = fmaf(__ldg(&wr[lane]), h[lane], 0.f);
            acc = fmaf(__ldg(&wr[lane + 32]), h[lane + 32], acc);
#pragma unroll
            for (int s = 16; s; s >>= 1) acc += __shfl_xor_sync(0xffffffffu, acc, s);
            if (lane == 0) out[n * 5 + c] = acc + fc2b[c];
        }
    }
}

extern "C" void kernel_launch(void* const* d_in, const int* in_sizes, int n_in,
                              void* d_out, int out_size) {
    const float* x0   = (const float*)d_in[0];
    const float* x1   = (const float*)d_in[1];
    const float* w1   = (const float*)d_in[2];
    const float* b1g  = (const float*)d_in[3];
    const float* b1b  = (const float*)d_in[4];
    const float* b1m  = (const float*)d_in[5];
    const float* b1v  = (const float*)d_in[6];
    const float* w2   = (const float*)d_in[7];
    const float* b2g  = (const float*)d_in[8];
    const float* b2b  = (const float*)d_in[9];
    const float* b2m  = (const float*)d_in[10];
    const float* b2v  = (const float*)d_in[11];
    const float* fc1w = (const float*)d_in[12];
    const float* fc1b = (const float*)d_in[13];
    const float* fc2w = (const float*)d_in[14];
    const float* fc2b = (const float*)d_in[15];

    cudaFuncSetAttribute(stageT_kernel,
                         cudaFuncAttributeMaxDynamicSharedMemorySize, SMEM_BYTES);

    prep_kernel<<<64, 256>>>(w1, b1g, b1b, b1m, b1v, b2g, b2b, b2m, b2v);
    dim3 gridT(4, 64, 64);
    stageT_kernel<<<gridT, 256, SMEM_BYTES>>>(x0, x1);
    stageB_kernel<<<64, 256>>>(w2);
    stageC_kernel<<<32, 256>>>(fc1w, fc1b, fc2w, fc2b, (float*)d_out);
}

// round 8
// speedup vs baseline: 1.0004x; 1.0004x over previous
#include <cuda_runtime.h>
#include <cuda_bf16.h>
#include <cstdint>

#define IC1 10
#define OC1 64
#define OC2 128
#define NB  64
#define EPS_CERT 0.006f

__device__ int      g_cnt[NB][OC1][9];  // S, Rf, Rl, Cf, Cl, q_tl, q_tr, q_bl, q_br
__device__ float    g_s2[NB][OC2];
__device__ float    g_inv1[OC1],  g_beta1[OC1], g_Kmar[OC1];
__device__ float    g_inv2[OC2],  g_beta2[OC2];
__device__ __align__(16) uint16_t g_Wt[144 * 72];   // bf16 weights, k-major (k=tap*16+ic)
__device__ int      g_list_cnt;
__device__ uint32_t g_list[1u << 26];               // worst-case: every window ambiguous

// ---------------- warp-mma helpers ----------------
__device__ __forceinline__ uint32_t smem_u32(const void* p) {
    uint32_t a;
    asm("{ .reg .u64 t; cvta.to.shared.u64 t, %1; cvt.u32.u64 %0, t; }" : "=r"(a) : "l"(p));
    return a;
}
__device__ __forceinline__ void ldsm_x4(uint32_t& r0, uint32_t& r1, uint32_t& r2, uint32_t& r3, uint32_t a) {
    asm volatile("ldmatrix.sync.aligned.m8n8.x4.shared.b16 {%0,%1,%2,%3}, [%4];"
                 : "=r"(r0), "=r"(r1), "=r"(r2), "=r"(r3) : "r"(a));
}
__device__ __forceinline__ void ldsm_x4_t(uint32_t& r0, uint32_t& r1, uint32_t& r2, uint32_t& r3, uint32_t a) {
    asm volatile("ldmatrix.sync.aligned.m8n8.x4.trans.shared.b16 {%0,%1,%2,%3}, [%4];"
                 : "=r"(r0), "=r"(r1), "=r"(r2), "=r"(r3) : "r"(a));
}
__device__ __forceinline__ void mma16816(float& c0, float& c1, float& c2, float& c3,
                                         uint32_t a0, uint32_t a1, uint32_t a2, uint32_t a3,
                                         uint32_t b0, uint32_t b1) {
    asm volatile("mma.sync.aligned.m16n8k16.row.col.f32.bf16.bf16.f32 "
                 "{%0,%1,%2,%3},{%4,%5,%6,%7},{%8,%9},{%0,%1,%2,%3};"
                 : "+f"(c0), "+f"(c1), "+f"(c2), "+f"(c3)
                 : "r"(a0), "r"(a1), "r"(a2), "r"(a3), "r"(b0), "r"(b1));
}

// ---------------- smem layout (bytes) ----------------
#define SM_BN    0        // float[192]: inv, beta, Kmar
#define SM_RED   768      // int[256]
#define SM_SPK   1792     // uchar[4096]
#define SM_CSQ   5888     // float[396]
#define SM_XN    7472     // float[256]
#define SM_LCNT  8496     // int + base int
#define SM_LIST  8512     // u32[4096]
#define SM_SHI   24896    // bf16[6*66*16] = 12672 B
#define SM_A     37632    // 256 rows x 48 B = 12288
#define SM_B     49920    // 144 rows x 144 B = 20736
#define SMEM_BYTES 70656

// ---------------------------------------------------------------------------
// prep: zero counters/list, fold BN, bf16 weight image + certified margins
// ---------------------------------------------------------------------------
__global__ void prep_kernel(const float* __restrict__ w1,
                            const float* __restrict__ g1, const float* __restrict__ b1,
                            const float* __restrict__ m1, const float* __restrict__ v1,
                            const float* __restrict__ g2, const float* __restrict__ b2,
                            const float* __restrict__ m2, const float* __restrict__ v2) {
    int gid = blockIdx.x * blockDim.x + threadIdx.x;
    int* c = &g_cnt[0][0][0];
    for (int i = gid; i < NB * OC1 * 9; i += gridDim.x * blockDim.x) c[i] = 0;
    if (gid == 0) g_list_cnt = 0;
    if (blockIdx.x == 0) {
        int t = threadIdx.x;
        if (t < OC1) {
            float inv = g1[t] / sqrtf(v1[t] + 1e-5f);
            g_inv1[t] = inv;
            g_beta1[t] = b1[t] - m1[t] * inv;
            float nrm = 0.f;
            for (int k = 0; k < 90; ++k) {
                float wv = __bfloat162float(__float2bfloat16(__ldg(&w1[t * 90 + k])));
                nrm = fmaf(wv, wv, nrm);
            }
            g_Kmar[t] = EPS_CERT * sqrtf(nrm) * fabsf(inv) * 1.000001f;
        }
        if (t < OC2) {
            float inv = g2[t] / sqrtf(v2[t] + 1e-5f);
            g_inv2[t] = inv;
            g_beta2[t] = b2[t] - m2[t] * inv;
        }
    }
    if (gid < 144 * 72) {
        int k = gid / 72, oc = gid % 72;
        int j = k >> 4, ic = k & 15;
        float v = (ic < IC1 && oc < OC1) ? __ldg(&w1[oc * 90 + ic * 9 + j]) : 0.f;
        g_Wt[gid] = __bfloat16_as_ushort(__float2bfloat16(v));
    }
}

// ---------------------------------------------------------------------------
// stage T: single-pass bf16 mma.sync conv + certified spike classification
// grid (4, 64, 64): x = 64-col strip, y = 4 conv rows, z = n. 256 threads.
// ---------------------------------------------------------------------------
__global__ __launch_bounds__(256, 2) void stageT_kernel(const float* __restrict__ x0,
                                                        const float* __restrict__ x1) {
    extern __shared__ char smem[];
    const uint32_t sb = smem_u32(smem);
    float*         sBN  = (float*)(smem + SM_BN);
    int*           sred = (int*)(smem + SM_RED);
    unsigned char* spk  = (unsigned char*)(smem + SM_SPK);
    float*         sCSQ = (float*)(smem + SM_CSQ);
    float*         sXN  = (float*)(smem + SM_XN);
    int*           sLC  = (int*)(smem + SM_LCNT);
    uint32_t*      sList = (uint32_t*)(smem + SM_LIST);
    uint16_t*      sh   = (uint16_t*)(smem + SM_SHI);

    const int tid = threadIdx.x, w = tid >> 5, l = tid & 31;
    const int bx = blockIdx.x, by = blockIdx.y, n = blockIdx.z;
    const float* __restrict__ x = (n < 32) ? x0 : x1;
    const int b = n & 31;

    if (tid < 64) {
        sBN[tid]       = __ldg(&g_inv1[tid]);
        sBN[64 + tid]  = __ldg(&g_beta1[tid]);
        sBN[128 + tid] = __ldg(&g_Kmar[tid]);
    }
    {   // B tile
        const uint4* gw = (const uint4*)g_Wt;
        uint4* sB4 = (uint4*)(smem + SM_B);
        for (int i = tid; i < 1296; i += 256) sB4[i] = __ldg(&gw[i]);
    }
    {   // zero staging + spike map
        uint4 z = make_uint4(0, 0, 0, 0);
        uint4* s4 = (uint4*)(smem + SM_SHI);
        for (int i = tid; i < 792; i += 256) s4[i] = z;
        ((uint4*)spk)[tid] = z;
        if (tid == 0) sLC[0] = 0;
    }
    __syncthreads();

    // staging: bf16 values + per-cell sum of squares
    {
        const int gy0 = 4 * by - 1, gx0 = 64 * bx - 1;
        for (int cell = tid; cell < 396; cell += 256) {
            int rw = cell / 66, cl = cell % 66;
            int gy = gy0 + rw, gx = gx0 + cl;
            bool ok = ((unsigned)gy < 256u) && ((unsigned)gx < 256u);
            float q = 0.f;
            uint16_t* dst = sh + cell * 16;
#pragma unroll
            for (int ic = 0; ic < IC1; ++ic) {
                float v = ok ? __ldg(&x[((b * IC1 + ic) * 256 + gy) * 256 + gx]) : 0.f;
                __nv_bfloat16 h = __float2bfloat16(v);
                dst[ic] = __bfloat16_as_ushort(h);
                float hv = __bfloat162float(h);
                q = fmaf(hv, hv, q);
            }
            sCSQ[cell] = q;
        }
    }
    __syncthreads();

    // per-position patch norm
    {
        int r = tid >> 6, c = tid & 63;
        float s = 0.f;
#pragma unroll
        for (int ky = 0; ky < 3; ++ky)
#pragma unroll
            for (int kx = 0; kx < 3; ++kx)
                s += sCSQ[(r + ky) * 66 + (c + kx)];
        sXN[tid] = sqrtf(s) * 1.000001f;
    }

    // A-row position for build
    const int rt = tid & 15, mtp = tid >> 4;
    const int v_ = rt >> 3, u_ = rt & 1, j_ = (rt & 7) >> 1;
    const int Q_ = 4 * mtp + j_;
    const int r_local = 2 * (Q_ >> 5) + u_;
    const int c_local = 2 * (Q_ & 31) + v_;
    const uint32_t aoff = (uint32_t)((l & 7) + ((l >> 3) & 1) * 8) * 48u + (uint32_t)(l >> 4) * 16u;

    float acc[2][8][4];
#pragma unroll
    for (int a = 0; a < 2; ++a)
#pragma unroll
        for (int nt = 0; nt < 8; ++nt)
#pragma unroll
            for (int q = 0; q < 4; ++q) acc[a][nt][q] = 0.f;

#pragma unroll 1
    for (int s = 0; s < 9; ++s) {
        const int ky = s / 3, kx = s % 3;
        {   // build A (copies from ic-interleaved staging)
            const uint32_t so = (uint32_t)(((r_local + ky) * 66 + (c_local + kx)) * 32);
            const uint4* src = (const uint4*)((const char*)sh + so);
            uint4* dh = (uint4*)(smem + SM_A + tid * 48);
            uint4 h0 = src[0], h1 = src[1];
            dh[0] = h0; dh[1] = h1;
        }
        __syncthreads();

        uint32_t A[2][4];
#pragma unroll
        for (int m2 = 0; m2 < 2; ++m2)
            ldsm_x4(A[m2][0], A[m2][1], A[m2][2], A[m2][3],
                    sb + SM_A + (uint32_t)((2 * w + m2) * 16) * 48u + aoff);
        uint32_t bf[8][2];
        const uint32_t bbase = sb + SM_B + ((uint32_t)s * 16u + (uint32_t)(l & 15)) * 144u;
#pragma unroll
        for (int ntp = 0; ntp < 4; ++ntp)
            ldsm_x4_t(bf[2 * ntp][0], bf[2 * ntp][1], bf[2 * ntp + 1][0], bf[2 * ntp + 1][1],
                      bbase + (uint32_t)(2 * ntp + (l >> 4)) * 16u);
#pragma unroll
        for (int nt = 0; nt < 8; ++nt)
#pragma unroll
            for (int m2 = 0; m2 < 2; ++m2) {
                float* c = acc[m2][nt];
                mma16816(c[0], c[1], c[2], c[3],
                         A[m2][0], A[m2][1], A[m2][2], A[m2][3], bf[nt][0], bf[nt][1]);
            }
        __syncthreads();
    }

    // epilogue: BN affine + certified interval pooling
    {
        const int a_ = l >> 2;
        const bool lead = (a_ & 1) == 0;
        const int jq = a_ >> 1;
        const int q0 = 2 * (l & 3);
        const int u = a_ & 1;
#pragma unroll
        for (int m2 = 0; m2 < 2; ++m2) {
            const int mt = 2 * w + m2;
            const int Qq = 4 * mt + jq;
            const int rA = 2 * (Qq >> 5) + u;
            const int cA = 2 * (Qq & 31);
            const float xnA = sXN[rA * 64 + cA];
            const float xnB = sXN[rA * 64 + cA + 1];
#pragma unroll
            for (int nt = 0; nt < 8; ++nt) {
                const int oc0 = nt * 8 + q0, oc1 = oc0 + 1;
                const float* c = acc[m2][nt];
                float z0 = fmaf(c[0], sBN[oc0], sBN[64 + oc0]);
                float z1 = fmaf(c[1], sBN[oc1], sBN[64 + oc1]);
                float z2 = fmaf(c[2], sBN[oc0], sBN[64 + oc0]);
                float z3 = fmaf(c[3], sBN[oc1], sBN[64 + oc1]);
                const float K0 = sBN[128 + oc0], K1 = sBN[128 + oc1];
                float lo0 = fmaxf(z0 - K0 * xnA, z2 - K0 * xnB);
                float hi0 = fmaxf(z0 + K0 * xnA, z2 + K0 * xnB);
                float lo1 = fmaxf(z1 - K1 * xnA, z3 - K1 * xnB);
                float hi1 = fmaxf(z1 + K1 * xnA, z3 + K1 * xnB);
                lo0 = fmaxf(lo0, __shfl_xor_sync(0xffffffffu, lo0, 4));
                hi0 = fmaxf(hi0, __shfl_xor_sync(0xffffffffu, hi0, 4));
                lo1 = fmaxf(lo1, __shfl_xor_sync(0xffffffffu, lo1, 4));
                hi1 = fmaxf(hi1, __shfl_xor_sync(0xffffffffu, hi1, 4));
                if (lead) {
                    const int py = 2 * by + (Qq >> 5);
                    const int px = 32 * bx + (Qq & 31);
                    bool sp0 = lo0 > 1.0f;
                    spk[Qq * 64 + oc0] = sp0;
                    if (!sp0 && hi0 > 1.0f) {
                        int idx = atomicAdd(&sLC[0], 1);
                        sList[idx] = (((uint32_t)(n * 64 + oc0)) << 14) | ((uint32_t)py << 7) | (uint32_t)px;
                    }
                    bool sp1 = lo1 > 1.0f;
                    spk[Qq * 64 + oc1] = sp1;
                    if (!sp1 && hi1 > 1.0f) {
                        int idx = atomicAdd(&sLC[0], 1);
                        sList[idx] = (((uint32_t)(n * 64 + oc1)) << 14) | ((uint32_t)py << 7) | (uint32_t)px;
                    }
                }
            }
        }
    }
    __syncthreads();

    // reduce certain spikes -> aggregates; flush ambiguous list
    {
        const int oc = tid & 63, grp = tid >> 6;
        int s = 0;
#pragma unroll
        for (int q = 0; q < 16; ++q) s += spk[(grp * 16 + q) * 64 + oc];
        sred[grp * 64 + oc] = s;
    }
    if (tid == 0) sLC[1] = atomicAdd(&g_list_cnt, sLC[0]);
    __syncthreads();
    {
        const int cnt = sLC[0], base = sLC[1];
        for (int i = tid; i < cnt; i += 256) g_list[base + i] = sList[i];
    }
    if (tid < 64) {
        const int oc = tid;
        int Sf = sred[oc] + sred[64 + oc];
        int Sl = sred[128 + oc] + sred[192 + oc];
        int S = Sf + Sl;
        if (S) atomicAdd(&g_cnt[n][oc][0], S);
        if (by == 0 && Sf)  atomicAdd(&g_cnt[n][oc][1], Sf);
        if (by == 63 && Sl) atomicAdd(&g_cnt[n][oc][2], Sl);
        if (bx == 0) {
            int Cf = spk[0 * 64 + oc] + spk[32 * 64 + oc];
            if (Cf) atomicAdd(&g_cnt[n][oc][3], Cf);
            if (by == 0 && spk[0 * 64 + oc])   g_cnt[n][oc][5] = 1;
            if (by == 63 && spk[32 * 64 + oc]) g_cnt[n][oc][7] = 1;
        }
        if (bx == 3) {
            int Cl = spk[31 * 64 + oc] + spk[63 * 64 + oc];
            if (Cl) atomicAdd(&g_cnt[n][oc][4], Cl);
            if (by == 0 && spk[31 * 64 + oc])  g_cnt[n][oc][6] = 1;
            if (by == 63 && spk[63 * 64 + oc]) g_cnt[n][oc][8] = 1;
        }
    }
}

// ---------------------------------------------------------------------------
// fixup: exact fp32 recompute of ambiguous windows
// ---------------------------------------------------------------------------
__global__ __launch_bounds__(128) void fixup_kernel(const float* __restrict__ x0,
                                                    const float* __restrict__ x1,
                                                    const float* __restrict__ w1) {
    const int total = g_list_cnt;
    for (int i = blockIdx.x * blockDim.x + threadIdx.x; i < total; i += gridDim.x * blockDim.x) {
        const uint32_t e = g_list[i];
        const int px = e & 127, py = (e >> 7) & 127;
        const int noc = e >> 14, oc = noc & 63, n = noc >> 6;
        const float* __restrict__ x = (n < 32) ? x0 : x1;
        const int b = n & 31;
        float a0 = 0.f, a1 = 0.f, a2 = 0.f, a3 = 0.f;
        const int gy0 = 2 * py - 1, gx0 = 2 * px - 1;
#pragma unroll 1
        for (int ic = 0; ic < IC1; ++ic) {
            float v[4][4];
#pragma unroll
            for (int iy = 0; iy < 4; ++iy)
#pragma unroll
                for (int ix = 0; ix < 4; ++ix) {
                    int gy = gy0 + iy, gx = gx0 + ix;
                    v[iy][ix] = (((unsigned)gy < 256u) && ((unsigned)gx < 256u))
                                ? __ldg(&x[((b * IC1 + ic) * 256 + gy) * 256 + gx]) : 0.f;
                }
            const float* wr = w1 + oc * 90 + ic * 9;
#pragma unroll
            for (int ky = 0; ky < 3; ++ky)
#pragma unroll
                for (int kx = 0; kx < 3; ++kx) {
                    float wv = __ldg(&wr[ky * 3 + kx]);
                    a0 = fmaf(wv, v[ky][kx],         a0);
                    a1 = fmaf(wv, v[ky][kx + 1],     a1);
                    a2 = fmaf(wv, v[ky + 1][kx],     a2);
                    a3 = fmaf(wv, v[ky + 1][kx + 1], a3);
                }
        }
        const float inv = __ldg(&g_inv1[oc]), bet = __ldg(&g_beta1[oc]);
        float zm = fmaxf(fmaxf(fmaf(a0, inv, bet), fmaf(a1, inv, bet)),
                         fmaxf(fmaf(a2, inv, bet), fmaf(a3, inv, bet)));
        if (zm > 1.0f) {
            atomicAdd(&g_cnt[n][oc][0], 1);
            if (py == 0)   atomicAdd(&g_cnt[n][oc][1], 1);
            if (py == 127) atomicAdd(&g_cnt[n][oc][2], 1);
            if (px == 0)   atomicAdd(&g_cnt[n][oc][3], 1);
            if (px == 127) atomicAdd(&g_cnt[n][oc][4], 1);
            if (py == 0 && px == 0)     g_cnt[n][oc][5] = 1;
            if (py == 0 && px == 127)   g_cnt[n][oc][6] = 1;
            if (py == 127 && px == 0)   g_cnt[n][oc][7] = 1;
            if (py == 127 && px == 127) g_cnt[n][oc][8] = 1;
        }
    }
}

// ---------------------------------------------------------------------------
// stage B: analytic conv2-mean via T aggregates, BN2, spike -> g_s2
// ---------------------------------------------------------------------------
__global__ __launch_bounds__(256) void stageB_kernel(const float* __restrict__ w2) {
    __shared__ __align__(16) float sT[OC1 * 9];
    const int n = blockIdx.x, tid = threadIdx.x;
    const int lane = tid & 31, warp = tid >> 5;
    if (tid < OC1) {
        const int* c = g_cnt[n][tid];
        int S = c[0], Rf = c[1], Rl = c[2], Cf = c[3], Cl = c[4];
        int Re[3] = {Rl, 0, Rf};
        int Ce[3] = {Cl, 0, Cf};
        int Q[9]  = {c[8], 0, c[7],  0, 0, 0,  c[6], 0, c[5]};
#pragma unroll
        for (int k = 0; k < 9; ++k)
            sT[tid * 9 + k] = (float)(S - Re[k / 3] - Ce[k % 3] + Q[k]);
    }
    __syncthreads();
#pragma unroll 1
    for (int i = 0; i < 16; ++i) {
        const int o = warp * 16 + i;
        const float* wr = w2 + o * 576;
        float acc = 0.f;
#pragma unroll
        for (int t = 0; t < 18; ++t) {
            int j = t * 32 + lane;
            acc = fmaf(__ldg(&wr[j]), sT[j], acc);
        }
#pragma unroll
        for (int s = 16; s; s >>= 1) acc += __shfl_xor_sync(0xffffffffu, acc, s);
        if (lane == 0) {
            float z = acc * (1.f / 16384.f);
            z = z * g_inv2[o] + g_beta2[o];
            g_s2[n][o] = (z > 1.f) ? 1.f : 0.f;
        }
    }
}

// ---------------------------------------------------------------------------
// stage C: feat = |s0 - s1|, fc1+relu, fc2  -> out (32,5)
// ---------------------------------------------------------------------------
__global__ __launch_bounds__(256) void stageC_kernel(const float* __restrict__ fc1w,
                                                     const float* __restrict__ fc1b,
                                                     const float* __restrict__ fc2w,
                                                     const float* __restrict__ fc2b,
                                                     float* __restrict__ out) {
    __shared__ float f[128];
    __shared__ float h[64];
    const int n = blockIdx.x, tid = threadIdx.x;
    const int lane = tid & 31, warp = tid >> 5;
    if (tid < 128) f[tid] = fabsf(g_s2[n][tid] - g_s2[n + 32][tid]);
    __syncthreads();
#pragma unroll 1
    for (int i = 0; i < 8; ++i) {
        const int k = warp * 8 + i;
        const float* wr = fc1w + k * 128;
        float acc = 0.f;
#pragma unroll
        for (int t = 0; t < 4; ++t) {
            int j = t * 32 + lane;
            acc = fmaf(__ldg(&wr[j]), f[j], acc);
        }
#pragma unroll
        for (int s = 16; s; s >>= 1) acc += __shfl_xor_sync(0xffffffffu, acc, s);
        if (lane == 0) h[k] = fmaxf(acc + fc1b[k], 0.f);
    }
    __syncthreads();
    if (warp == 0) {
#pragma unroll 1
        for (int c = 0; c < 5; ++c) {
            const float* wr = fc2w + c * 64;
            float acc = fmaf(__ldg(&wr[lane]), h[lane], 0.f);
            acc = fmaf(__ldg(&wr[lane + 32]), h[lane + 32], acc);
#pragma unroll
            for (int s = 16; s; s >>= 1) acc += __shfl_xor_sync(0xffffffffu, acc, s);
            if (lane == 0) out[n * 5 + c] = acc + fc2b[c];
        }
    }
}

extern "C" void kernel_launch(void* const* d_in, const int* in_sizes, int n_in,
                              void* d_out, int out_size) {
    const float* x0   = (const float*)d_in[0];
    const float* x1   = (const float*)d_in[1];
    const float* w1   = (const float*)d_in[2];
    const float* b1g  = (const float*)d_in[3];
    const float* b1b  = (const float*)d_in[4];
    const float* b1m  = (const float*)d_in[5];
    const float* b1v  = (const float*)d_in[6];
    const float* w2   = (const float*)d_in[7];
    const float* b2g  = (const float*)d_in[8];
    const float* b2b  = (const float*)d_in[9];
    const float* b2m  = (const float*)d_in[10];
    const float* b2v  = (const float*)d_in[11];
    const float* fc1w = (const float*)d_in[12];
    const float* fc1b = (const float*)d_in[13];
    const float* fc2w = (const float*)d_in[14];
    const float* fc2b = (const float*)d_in[15];

    cudaFuncSetAttribute(stageT_kernel,
                         cudaFuncAttributeMaxDynamicSharedMemorySize, SMEM_BYTES);

    prep_kernel<<<64, 256>>>(w1, b1g, b1b, b1m, b1v, b2g, b2b, b2m, b2v);
    dim3 gridT(4, 64, 64);
    stageT_kernel<<<gridT, 256, SMEM_BYTES>>>(x0, x1);
    fixup_kernel<<<2048, 128>>>(x0, x1, w1);
    stageB_kernel<<<64, 256>>>(w2);
    stageC_kernel<<<32, 256>>>(fc1w, fc1b, fc2w, fc2b, (float*)d_out);
}

// round 9
// speedup vs baseline: 1.0407x; 1.0403x over previous
#include <cuda_runtime.h>
#include <cuda_bf16.h>
#include <cstdint>

#define IC1 10
#define OC1 64
#define OC2 128
#define NB  64
#define EPS_CERT 0.006f

__device__ int      g_cnt[NB][OC1][9];  // S, Rf, Rl, Cf, Cl, q_tl, q_tr, q_bl, q_br
__device__ float    g_s2[NB][OC2];
__device__ float    g_inv1[OC1],  g_beta1[OC1], g_Kmar[OC1];
__device__ float    g_inv2[OC2],  g_beta2[OC2];
__device__ __align__(16) uint16_t g_Wt[144 * 72];   // bf16 weights, k-major (k=tap*16+ic)

// ---------------- warp-mma helpers ----------------
__device__ __forceinline__ uint32_t smem_u32(const void* p) {
    uint32_t a;
    asm("{ .reg .u64 t; cvta.to.shared.u64 t, %1; cvt.u32.u64 %0, t; }" : "=r"(a) : "l"(p));
    return a;
}
__device__ __forceinline__ void ldsm_x4(uint32_t& r0, uint32_t& r1, uint32_t& r2, uint32_t& r3, uint32_t a) {
    asm volatile("ldmatrix.sync.aligned.m8n8.x4.shared.b16 {%0,%1,%2,%3}, [%4];"
                 : "=r"(r0), "=r"(r1), "=r"(r2), "=r"(r3) : "r"(a));
}
__device__ __forceinline__ void ldsm_x4_t(uint32_t& r0, uint32_t& r1, uint32_t& r2, uint32_t& r3, uint32_t a) {
    asm volatile("ldmatrix.sync.aligned.m8n8.x4.trans.shared.b16 {%0,%1,%2,%3}, [%4];"
                 : "=r"(r0), "=r"(r1), "=r"(r2), "=r"(r3) : "r"(a));
}
__device__ __forceinline__ void mma16816(float& c0, float& c1, float& c2, float& c3,
                                         uint32_t a0, uint32_t a1, uint32_t a2, uint32_t a3,
                                         uint32_t b0, uint32_t b1) {
    asm volatile("mma.sync.aligned.m16n8k16.row.col.f32.bf16.bf16.f32 "
                 "{%0,%1,%2,%3},{%4,%5,%6,%7},{%8,%9},{%0,%1,%2,%3};"
                 : "+f"(c0), "+f"(c1), "+f"(c2), "+f"(c3)
                 : "r"(a0), "r"(a1), "r"(a2), "r"(a3), "r"(b0), "r"(b1));
}

// ---------------- smem layout (bytes) ----------------
#define SM_BN    0        // float[192]: inv, beta, Kmar
#define SM_RED   768      // int[256]
#define SM_SPK   1792     // uchar[4096]
#define SM_CSQ   5888     // float[396]
#define SM_XN    7472     // float[256]
#define SM_LCNT  8496     // int[2] (+pad)
#define SM_LIST  8512     // u16[4096]
#define SM_SHI   16704    // bf16[6*66*16] = 12672 B (A matrix, read in place)
#define SM_XF    29376    // float[396*10] = 15840 B (exact fp32 for fixup)
#define SM_B     45216    // 144 rows x 144 B = 20736
#define SMEM_BYTES 65952

// ---------------------------------------------------------------------------
// prep: zero counters, fold BN, bf16 weight image + certified margins
// ---------------------------------------------------------------------------
__global__ void prep_kernel(const float* __restrict__ w1,
                            const float* __restrict__ g1, const float* __restrict__ b1,
                            const float* __restrict__ m1, const float* __restrict__ v1,
                            const float* __restrict__ g2, const float* __restrict__ b2,
                            const float* __restrict__ m2, const float* __restrict__ v2) {
    int gid = blockIdx.x * blockDim.x + threadIdx.x;
    int* c = &g_cnt[0][0][0];
    for (int i = gid; i < NB * OC1 * 9; i += gridDim.x * blockDim.x) c[i] = 0;
    if (blockIdx.x == 0) {
        int t = threadIdx.x;
        if (t < OC1) {
            float inv = g1[t] / sqrtf(v1[t] + 1e-5f);
            g_inv1[t] = inv;
            g_beta1[t] = b1[t] - m1[t] * inv;
            float nrm = 0.f;
            for (int k = 0; k < 90; ++k) {
                float wv = __bfloat162float(__float2bfloat16(__ldg(&w1[t * 90 + k])));
                nrm = fmaf(wv, wv, nrm);
            }
            g_Kmar[t] = EPS_CERT * sqrtf(nrm) * fabsf(inv) * 1.000001f;
        }
        if (t < OC2) {
            float inv = g2[t] / sqrtf(v2[t] + 1e-5f);
            g_inv2[t] = inv;
            g_beta2[t] = b2[t] - m2[t] * inv;
        }
    }
    if (gid < 144 * 72) {
        int k = gid / 72, oc = gid % 72;
        int j = k >> 4, ic = k & 15;
        float v = (ic < IC1 && oc < OC1) ? __ldg(&w1[oc * 90 + ic * 9 + j]) : 0.f;
        g_Wt[gid] = __bfloat16_as_ushort(__float2bfloat16(v));
    }
}

// ---------------------------------------------------------------------------
// stage T: bf16 mma.sync conv (A via direct ldmatrix from staging, barrier-free
// mainloop) + certified interval pooling + in-block exact fixup
// grid (4, 64, 64): x = 64-col strip, y = 4 conv rows, z = n. 256 threads.
// ---------------------------------------------------------------------------
__global__ __launch_bounds__(256, 2) void stageT_kernel(const float* __restrict__ x0,
                                                        const float* __restrict__ x1,
                                                        const float* __restrict__ w1) {
    extern __shared__ char smem[];
    const uint32_t sb = smem_u32(smem);
    float*         sBN  = (float*)(smem + SM_BN);
    int*           sred = (int*)(smem + SM_RED);
    unsigned char* spk  = (unsigned char*)(smem + SM_SPK);
    float*         sCSQ = (float*)(smem + SM_CSQ);
    float*         sXN  = (float*)(smem + SM_XN);
    int*           sLC  = (int*)(smem + SM_LCNT);
    uint16_t*      sList = (uint16_t*)(smem + SM_LIST);
    uint16_t*      sh   = (uint16_t*)(smem + SM_SHI);
    float*         sXF  = (float*)(smem + SM_XF);

    const int tid = threadIdx.x, w = tid >> 5, l = tid & 31;
    const int bx = blockIdx.x, by = blockIdx.y, n = blockIdx.z;
    const float* __restrict__ x = (n < 32) ? x0 : x1;
    const int b = n & 31;

    if (tid < 64) {
        sBN[tid]       = __ldg(&g_inv1[tid]);
        sBN[64 + tid]  = __ldg(&g_beta1[tid]);
        sBN[128 + tid] = __ldg(&g_Kmar[tid]);
    }
    {   // B tile
        const uint4* gw = (const uint4*)g_Wt;
        uint4* sB4 = (uint4*)(smem + SM_B);
        for (int i = tid; i < 1296; i += 256) sB4[i] = __ldg(&gw[i]);
    }
    {   // zero bf16 staging (ic padding + halo) + spike map + list count
        uint4 z = make_uint4(0, 0, 0, 0);
        uint4* s4 = (uint4*)(smem + SM_SHI);
        for (int i = tid; i < 792; i += 256) s4[i] = z;
        ((uint4*)spk)[tid] = z;
        if (tid == 0) sLC[0] = 0;
    }
    __syncthreads();

    // staging: fp32 (exact) + bf16 + per-cell sum of squares
    {
        const int gy0 = 4 * by - 1, gx0 = 64 * bx - 1;
        for (int cell = tid; cell < 396; cell += 256) {
            int rw = cell / 66, cl = cell % 66;
            int gy = gy0 + rw, gx = gx0 + cl;
            bool ok = ((unsigned)gy < 256u) && ((unsigned)gx < 256u);
            float q = 0.f;
            uint16_t* dst = sh + cell * 16;
            float* dxf = sXF + cell * 10;
#pragma unroll
            for (int ic = 0; ic < IC1; ++ic) {
                float v = ok ? __ldg(&x[((b * IC1 + ic) * 256 + gy) * 256 + gx]) : 0.f;
                dxf[ic] = v;
                __nv_bfloat16 h = __float2bfloat16(v);
                dst[ic] = __bfloat16_as_ushort(h);
                float hv = __bfloat162float(h);
                q = fmaf(hv, hv, q);
            }
            sCSQ[cell] = q;
        }
    }
    __syncthreads();

    // per-position patch norm (positions: r = tid>>6 in 0..3, c = tid&63)
    {
        int r = tid >> 6, c = tid & 63;
        float s = 0.f;
#pragma unroll
        for (int ky = 0; ky < 3; ++ky)
#pragma unroll
            for (int kx = 0; kx < 3; ++kx)
                s += sCSQ[(r + ky) * 66 + (c + kx)];
        sXN[tid] = sqrtf(s) * 1.000001f;
    }
    __syncthreads();

    // per-lane A base addresses (read A fragments directly from staging)
    uint32_t addrA[2];
#pragma unroll
    for (int m2 = 0; m2 < 2; ++m2) {
        const int arow = (l & 7) | (((l >> 3) & 1) << 3);
        const int R = (2 * w + m2) * 16 + arow;
        const int Q = 4 * (R >> 4) + ((R >> 1) & 3);
        const int u = R & 1, v = (R >> 3) & 1;
        const int r = 2 * (Q >> 5) + u;
        const int c = 2 * (Q & 31) + v;
        addrA[m2] = sb + SM_SHI + (uint32_t)((r * 66 + c) * 32) + (uint32_t)((l >> 4) * 16);
    }

    float acc[2][8][4];
#pragma unroll
    for (int a = 0; a < 2; ++a)
#pragma unroll
        for (int nt = 0; nt < 8; ++nt)
#pragma unroll
            for (int q = 0; q < 4; ++q) acc[a][nt][q] = 0.f;

    // barrier-free mainloop: 9 taps, A from staging, B from weight tile
#pragma unroll
    for (int s = 0; s < 9; ++s) {
        const uint32_t aoffs = (uint32_t)(((s / 3) * 66 + (s % 3)) * 32);
        uint32_t A[2][4];
#pragma unroll
        for (int m2 = 0; m2 < 2; ++m2)
            ldsm_x4(A[m2][0], A[m2][1], A[m2][2], A[m2][3], addrA[m2] + aoffs);
        uint32_t bf[8][2];
        const uint32_t bbase = sb + SM_B + ((uint32_t)s * 16u + (uint32_t)(l & 15)) * 144u;
#pragma unroll
        for (int ntp = 0; ntp < 4; ++ntp)
            ldsm_x4_t(bf[2 * ntp][0], bf[2 * ntp][1], bf[2 * ntp + 1][0], bf[2 * ntp + 1][1],
                      bbase + (uint32_t)(2 * ntp + (l >> 4)) * 16u);
#pragma unroll
        for (int nt = 0; nt < 8; ++nt)
#pragma unroll
            for (int m2 = 0; m2 < 2; ++m2) {
                float* c = acc[m2][nt];
                mma16816(c[0], c[1], c[2], c[3],
                         A[m2][0], A[m2][1], A[m2][2], A[m2][3], bf[nt][0], bf[nt][1]);
            }
    }

    // epilogue: BN affine + certified interval pooling; ambiguous -> shared list
    {
        const int a_ = l >> 2;
        const bool lead = (a_ & 1) == 0;
        const int jq = a_ >> 1;
        const int q0 = 2 * (l & 3);
        const int u = a_ & 1;
#pragma unroll
        for (int m2 = 0; m2 < 2; ++m2) {
            const int mt = 2 * w + m2;
            const int Qq = 4 * mt + jq;
            const int rA = 2 * (Qq >> 5) + u;
            const int cA = 2 * (Qq & 31);
            const float xnA = sXN[rA * 64 + cA];
            const float xnB = sXN[rA * 64 + cA + 1];
#pragma unroll
            for (int nt = 0; nt < 8; ++nt) {
                const int oc0 = nt * 8 + q0, oc1 = oc0 + 1;
                const float* c = acc[m2][nt];
                float z0 = fmaf(c[0], sBN[oc0], sBN[64 + oc0]);
                float z1 = fmaf(c[1], sBN[oc1], sBN[64 + oc1]);
                float z2 = fmaf(c[2], sBN[oc0], sBN[64 + oc0]);
                float z3 = fmaf(c[3], sBN[oc1], sBN[64 + oc1]);
                const float K0 = sBN[128 + oc0], K1 = sBN[128 + oc1];
                float lo0 = fmaxf(z0 - K0 * xnA, z2 - K0 * xnB);
                float hi0 = fmaxf(z0 + K0 * xnA, z2 + K0 * xnB);
                float lo1 = fmaxf(z1 - K1 * xnA, z3 - K1 * xnB);
                float hi1 = fmaxf(z1 + K1 * xnA, z3 + K1 * xnB);
                lo0 = fmaxf(lo0, __shfl_xor_sync(0xffffffffu, lo0, 4));
                hi0 = fmaxf(hi0, __shfl_xor_sync(0xffffffffu, hi0, 4));
                lo1 = fmaxf(lo1, __shfl_xor_sync(0xffffffffu, lo1, 4));
                hi1 = fmaxf(hi1, __shfl_xor_sync(0xffffffffu, hi1, 4));
                if (lead) {
                    bool sp0 = lo0 > 1.0f;
                    spk[Qq * 64 + oc0] = sp0;
                    if (!sp0 && hi0 > 1.0f) {
                        int idx = atomicAdd(&sLC[0], 1);
                        sList[idx] = (uint16_t)(Qq * 64 + oc0);
                    }
                    bool sp1 = lo1 > 1.0f;
                    spk[Qq * 64 + oc1] = sp1;
                    if (!sp1 && hi1 > 1.0f) {
                        int idx = atomicAdd(&sLC[0], 1);
                        sList[idx] = (uint16_t)(Qq * 64 + oc1);
                    }
                }
            }
        }
    }
    __syncthreads();

    // in-block exact fixup of ambiguous windows (fp32 from smem)
    {
        const int cnt = sLC[0];
        for (int i = tid; i < cnt; i += 256) {
            const int e = sList[i];
            const int oc = e & 63, Q = e >> 6;
            const int r0 = 2 * (Q >> 5), c0 = 2 * (Q & 31);
            float a0 = 0.f, a1 = 0.f, a2 = 0.f, a3 = 0.f;
#pragma unroll 1
            for (int ic = 0; ic < IC1; ++ic) {
                float v[4][4];
#pragma unroll
                for (int iy = 0; iy < 4; ++iy)
#pragma unroll
                    for (int ix = 0; ix < 4; ++ix)
                        v[iy][ix] = sXF[((r0 + iy) * 66 + (c0 + ix)) * 10 + ic];
                const float* wr = w1 + oc * 90 + ic * 9;
#pragma unroll
                for (int ky = 0; ky < 3; ++ky)
#pragma unroll
                    for (int kx = 0; kx < 3; ++kx) {
                        float wv = __ldg(&wr[ky * 3 + kx]);
                        a0 = fmaf(wv, v[ky][kx],         a0);
                        a1 = fmaf(wv, v[ky][kx + 1],     a1);
                        a2 = fmaf(wv, v[ky + 1][kx],     a2);
                        a3 = fmaf(wv, v[ky + 1][kx + 1], a3);
                    }
            }
            const float inv = sBN[oc], bet = sBN[64 + oc];
            float zm = fmaxf(fmaxf(fmaf(a0, inv, bet), fmaf(a1, inv, bet)),
                             fmaxf(fmaf(a2, inv, bet), fmaf(a3, inv, bet)));
            spk[e] = (zm > 1.0f);
        }
    }
    __syncthreads();

    // reduce spike map -> aggregates
    {
        const int oc = tid & 63, grp = tid >> 6;
        int s = 0;
#pragma unroll
        for (int q = 0; q < 16; ++q) s += spk[(grp * 16 + q) * 64 + oc];
        sred[grp * 64 + oc] = s;
    }
    __syncthreads();
    if (tid < 64) {
        const int oc = tid;
        int Sf = sred[oc] + sred[64 + oc];          // quads 0-31 (pooled row 2by)
        int Sl = sred[128 + oc] + sred[192 + oc];   // quads 32-63 (pooled row 2by+1)
        int S = Sf + Sl;
        if (S) atomicAdd(&g_cnt[n][oc][0], S);
        if (by == 0 && Sf)  atomicAdd(&g_cnt[n][oc][1], Sf);
        if (by == 63 && Sl) atomicAdd(&g_cnt[n][oc][2], Sl);
        if (bx == 0) {
            int Cf = spk[0 * 64 + oc] + spk[32 * 64 + oc];
            if (Cf) atomicAdd(&g_cnt[n][oc][3], Cf);
            if (by == 0 && spk[0 * 64 + oc])   g_cnt[n][oc][5] = 1;
            if (by == 63 && spk[32 * 64 + oc]) g_cnt[n][oc][7] = 1;
        }
        if (bx == 3) {
            int Cl = spk[31 * 64 + oc] + spk[63 * 64 + oc];
            if (Cl) atomicAdd(&g_cnt[n][oc][4], Cl);
            if (by == 0 && spk[31 * 64 + oc])  g_cnt[n][oc][6] = 1;
            if (by == 63 && spk[63 * 64 + oc]) g_cnt[n][oc][8] = 1;
        }
    }
}

// ---------------------------------------------------------------------------
// stage B: analytic conv2-mean via T aggregates, BN2, spike -> g_s2
// ---------------------------------------------------------------------------
__global__ __launch_bounds__(256) void stageB_kernel(const float* __restrict__ w2) {
    __shared__ __align__(16) float sT[OC1 * 9];
    const int n = blockIdx.x, tid = threadIdx.x;
    const int lane = tid & 31, warp = tid >> 5;
    if (tid < OC1) {
        const int* c = g_cnt[n][tid];
        int S = c[0], Rf = c[1], Rl = c[2], Cf = c[3], Cl = c[4];
        int Re[3] = {Rl, 0, Rf};
        int Ce[3] = {Cl, 0, Cf};
        int Q[9]  = {c[8], 0, c[7],  0, 0, 0,  c[6], 0, c[5]};
#pragma unroll
        for (int k = 0; k < 9; ++k)
            sT[tid * 9 + k] = (float)(S - Re[k / 3] - Ce[k % 3] + Q[k]);
    }
    __syncthreads();
#pragma unroll 1
    for (int i = 0; i < 16; ++i) {
        const int o = warp * 16 + i;
        const float* wr = w2 + o * 576;
        float acc = 0.f;
#pragma unroll
        for (int t = 0; t < 18; ++t) {
            int j = t * 32 + lane;
            acc = fmaf(__ldg(&wr[j]), sT[j], acc);
        }
#pragma unroll
        for (int s = 16; s; s >>= 1) acc += __shfl_xor_sync(0xffffffffu, acc, s);
        if (lane == 0) {
            float z = acc * (1.f / 16384.f);
            z = z * g_inv2[o] + g_beta2[o];
            g_s2[n][o] = (z > 1.f) ? 1.f : 0.f;
        }
    }
}

// ---------------------------------------------------------------------------
// stage C: feat = |s0 - s1|, fc1+relu, fc2  -> out (32,5)
// ---------------------------------------------------------------------------
__global__ __launch_bounds__(256) void stageC_kernel(const float* __restrict__ fc1w,
                                                     const float* __restrict__ fc1b,
                                                     const float* __restrict__ fc2w,
                                                     const float* __restrict__ fc2b,
                                                     float* __restrict__ out) {
    __shared__ float f[128];
    __shared__ float h[64];
    const int n = blockIdx.x, tid = threadIdx.x;
    const int lane = tid & 31, warp = tid >> 5;
    if (tid < 128) f[tid] = fabsf(g_s2[n][tid] - g_s2[n + 32][tid]);
    __syncthreads();
#pragma unroll 1
    for (int i = 0; i < 8; ++i) {
        const int k = warp * 8 + i;
        const float* wr = fc1w + k * 128;
        float acc = 0.f;
#pragma unroll
        for (int t = 0; t < 4; ++t) {
            int j = t * 32 + lane;
            acc = fmaf(__ldg(&wr[j]), f[j], acc);
        }
#pragma unroll
        for (int s = 16; s; s >>= 1) acc += __shfl_xor_sync(0xffffffffu, acc, s);
        if (lane == 0) h[k] = fmaxf(acc + fc1b[k], 0.f);
    }
    __syncthreads();
    if (warp == 0) {
#pragma unroll 1
        for (int c = 0; c < 5; ++c) {
            const float* wr = fc2w + c * 64;
            float acc = fmaf(__ldg(&wr[lane]), h[lane], 0.f);
            acc = fmaf(__ldg(&wr[lane + 32]), h[lane + 32], acc);
#pragma unroll
            for (int s = 16; s; s >>= 1) acc += __shfl_xor_sync(0xffffffffu, acc, s);
            if (lane == 0) out[n * 5 + c] = acc + fc2b[c];
        }
    }
}

extern "C" void kernel_launch(void* const* d_in, const int* in_sizes, int n_in,
                              void* d_out, int out_size) {
    const float* x0   = (const float*)d_in[0];
    const float* x1   = (const float*)d_in[1];
    const float* w1   = (const float*)d_in[2];
    const float* b1g  = (const float*)d_in[3];
    const float* b1b  = (const float*)d_in[4];
    const float* b1m  = (const float*)d_in[5];
    const float* b1v  = (const float*)d_in[6];
    const float* w2   = (const float*)d_in[7];
    const float* b2g  = (const float*)d_in[8];
    const float* b2b  = (const float*)d_in[9];
    const float* b2m  = (const float*)d_in[10];
    const float* b2v  = (const float*)d_in[11];
    const float* fc1w = (const float*)d_in[12];
    const float* fc1b = (const float*)d_in[13];
    const float* fc2w = (const float*)d_in[14];
    const float* fc2b = (const float*)d_in[15];

    cudaFuncSetAttribute(stageT_kernel,
                         cudaFuncAttributeMaxDynamicSharedMemorySize, SMEM_BYTES);

    prep_kernel<<<64, 256>>>(w1, b1g, b1b, b1m, b1v, b2g, b2b, b2m, b2v);
    dim3 gridT(4, 64, 64);
    stageT_kernel<<<gridT, 256, SMEM_BYTES>>>(x0, x1, w1);
    stageB_kernel<<<64, 256>>>(w2);
    stageC_kernel<<<32, 256>>>(fc1w, fc1b, fc2w, fc2b, (float*)d_out);
}

// round 10
// speedup vs baseline: 1.0559x; 1.0146x over previous
#include <cuda_runtime.h>
#include <cuda_bf16.h>
#include <cstdint>

#define IC1 10
#define OC1 64
#define OC2 128
#define NB  64
#define EPS_CERT 0.006f
#define CW 67   // staging row stride in cells (padded: 67*32B = 2144B ≡ 96 mod 128)

__device__ int      g_cnt[NB][OC1][9];  // S, Rf, Rl, Cf, Cl, q_tl, q_tr, q_bl, q_br
__device__ float    g_s2[NB][OC2];
__device__ float    g_inv1[OC1],  g_beta1[OC1], g_Kmar[OC1];
__device__ float    g_inv2[OC2],  g_beta2[OC2];
__device__ __align__(16) uint16_t g_Wt[144 * 72];   // bf16 weights, k-major (k=tap*16+ic)

// ---------------- warp-mma helpers ----------------
__device__ __forceinline__ uint32_t smem_u32(const void* p) {
    uint32_t a;
    asm("{ .reg .u64 t; cvta.to.shared.u64 t, %1; cvt.u32.u64 %0, t; }" : "=r"(a) : "l"(p));
    return a;
}
__device__ __forceinline__ void ldsm_x4(uint32_t& r0, uint32_t& r1, uint32_t& r2, uint32_t& r3, uint32_t a) {
    asm volatile("ldmatrix.sync.aligned.m8n8.x4.shared.b16 {%0,%1,%2,%3}, [%4];"
                 : "=r"(r0), "=r"(r1), "=r"(r2), "=r"(r3) : "r"(a));
}
__device__ __forceinline__ void ldsm_x4_t(uint32_t& r0, uint32_t& r1, uint32_t& r2, uint32_t& r3, uint32_t a) {
    asm volatile("ldmatrix.sync.aligned.m8n8.x4.trans.shared.b16 {%0,%1,%2,%3}, [%4];"
                 : "=r"(r0), "=r"(r1), "=r"(r2), "=r"(r3) : "r"(a));
}
__device__ __forceinline__ void mma16816(float& c0, float& c1, float& c2, float& c3,
                                         uint32_t a0, uint32_t a1, uint32_t a2, uint32_t a3,
                                         uint32_t b0, uint32_t b1) {
    asm volatile("mma.sync.aligned.m16n8k16.row.col.f32.bf16.bf16.f32 "
                 "{%0,%1,%2,%3},{%4,%5,%6,%7},{%8,%9},{%0,%1,%2,%3};"
                 : "+f"(c0), "+f"(c1), "+f"(c2), "+f"(c3)
                 : "r"(a0), "r"(a1), "r"(a2), "r"(a3), "r"(b0), "r"(b1));
}

// ---------------- smem layout (bytes) ----------------
#define SM_BN    0        // float[192]: inv, beta, Kmar
#define SM_RED   768      // int[256]
#define SM_SPK   1792     // uchar[4096]
#define SM_CSQ   5888     // float[396]
#define SM_XN    7472     // float[256]
#define SM_LCNT  8496     // int[2] (+pad)
#define SM_LIST  8512     // u16[4096]
#define SM_SHI   16704    // bf16[6*CW*16] = 12864 B (A matrix, read in place)
#define SM_XF    29568    // float[396*10] = 15840 B (exact fp32 for fixup)
#define SM_B     45408    // 144 rows x 144 B = 20736
#define SMEM_BYTES 66144

// ---------------------------------------------------------------------------
// prep: zero counters, fold BN, bf16 weight image + certified margins
// ---------------------------------------------------------------------------
__global__ void prep_kernel(const float* __restrict__ w1,
                            const float* __restrict__ g1, const float* __restrict__ b1,
                            const float* __restrict__ m1, const float* __restrict__ v1,
                            const float* __restrict__ g2, const float* __restrict__ b2,
                            const float* __restrict__ m2, const float* __restrict__ v2) {
    int gid = blockIdx.x * blockDim.x + threadIdx.x;
    int* c = &g_cnt[0][0][0];
    for (int i = gid; i < NB * OC1 * 9; i += gridDim.x * blockDim.x) c[i] = 0;
    if (blockIdx.x == 0) {
        int t = threadIdx.x;
        if (t < OC1) {
            float inv = g1[t] / sqrtf(v1[t] + 1e-5f);
            g_inv1[t] = inv;
            g_beta1[t] = b1[t] - m1[t] * inv;
            float nrm = 0.f;
            for (int k = 0; k < 90; ++k) {
                float wv = __bfloat162float(__float2bfloat16(__ldg(&w1[t * 90 + k])));
                nrm = fmaf(wv, wv, nrm);
            }
            g_Kmar[t] = EPS_CERT * sqrtf(nrm) * fabsf(inv) * 1.000001f;
        }
        if (t < OC2) {
            float inv = g2[t] / sqrtf(v2[t] + 1e-5f);
            g_inv2[t] = inv;
            g_beta2[t] = b2[t] - m2[t] * inv;
        }
    }
    if (gid < 144 * 72) {
        int k = gid / 72, oc = gid % 72;
        int j = k >> 4, ic = k & 15;
        float v = (ic < IC1 && oc < OC1) ? __ldg(&w1[oc * 90 + ic * 9 + j]) : 0.f;
        g_Wt[gid] = __bfloat16_as_ushort(__float2bfloat16(v));
    }
}

// ---------------------------------------------------------------------------
// stage T: bf16 mma.sync conv, TWO nt-half passes (32 acc regs each, no spill
// possible) + certified interval pooling + in-block exact fixup
// grid (4, 64, 64): x = 64-col strip, y = 4 conv rows, z = n. 256 threads.
// ---------------------------------------------------------------------------
__global__ __launch_bounds__(256, 2) void stageT_kernel(const float* __restrict__ x0,
                                                        const float* __restrict__ x1,
                                                        const float* __restrict__ w1) {
    extern __shared__ char smem[];
    const uint32_t sb = smem_u32(smem);
    float*         sBN  = (float*)(smem + SM_BN);
    int*           sred = (int*)(smem + SM_RED);
    unsigned char* spk  = (unsigned char*)(smem + SM_SPK);
    float*         sCSQ = (float*)(smem + SM_CSQ);
    float*         sXN  = (float*)(smem + SM_XN);
    int*           sLC  = (int*)(smem + SM_LCNT);
    uint16_t*      sList = (uint16_t*)(smem + SM_LIST);
    uint16_t*      sh   = (uint16_t*)(smem + SM_SHI);
    float*         sXF  = (float*)(smem + SM_XF);

    const int tid = threadIdx.x, w = tid >> 5, l = tid & 31;
    const int bx = blockIdx.x, by = blockIdx.y, n = blockIdx.z;
    const float* __restrict__ x = (n < 32) ? x0 : x1;
    const int b = n & 31;

    if (tid < 64) {
        sBN[tid]       = __ldg(&g_inv1[tid]);
        sBN[64 + tid]  = __ldg(&g_beta1[tid]);
        sBN[128 + tid] = __ldg(&g_Kmar[tid]);
    }
    {   // B tile
        const uint4* gw = (const uint4*)g_Wt;
        uint4* sB4 = (uint4*)(smem + SM_B);
        for (int i = tid; i < 1296; i += 256) sB4[i] = __ldg(&gw[i]);
    }
    {   // zero bf16 staging (ic padding + halo + row pad) + spike map + count
        uint4 z = make_uint4(0, 0, 0, 0);
        uint4* s4 = (uint4*)(smem + SM_SHI);
        for (int i = tid; i < 804; i += 256) s4[i] = z;
        ((uint4*)spk)[tid] = z;
        if (tid == 0) sLC[0] = 0;
    }
    __syncthreads();

    // staging: fp32 (exact) + bf16 + per-cell sum of squares
    {
        const int gy0 = 4 * by - 1, gx0 = 64 * bx - 1;
        for (int cell = tid; cell < 396; cell += 256) {
            int rw = cell / 66, cl = cell % 66;
            int gy = gy0 + rw, gx = gx0 + cl;
            bool ok = ((unsigned)gy < 256u) && ((unsigned)gx < 256u);
            float q = 0.f;
            uint16_t* dst = sh + (rw * CW + cl) * 16;
            float* dxf = sXF + cell * 10;
#pragma unroll
            for (int ic = 0; ic < IC1; ++ic) {
                float v = ok ? __ldg(&x[((b * IC1 + ic) * 256 + gy) * 256 + gx]) : 0.f;
                dxf[ic] = v;
                __nv_bfloat16 h = __float2bfloat16(v);
                dst[ic] = __bfloat16_as_ushort(h);
                float hv = __bfloat162float(h);
                q = fmaf(hv, hv, q);
            }
            sCSQ[cell] = q;
        }
    }
    __syncthreads();

    // per-position patch norm (positions: r = tid>>6 in 0..3, c = tid&63)
    {
        int r = tid >> 6, c = tid & 63;
        float s = 0.f;
#pragma unroll
        for (int ky = 0; ky < 3; ++ky)
#pragma unroll
            for (int kx = 0; kx < 3; ++kx)
                s += sCSQ[(r + ky) * 66 + (c + kx)];
        sXN[tid] = sqrtf(s) * 1.000001f;
    }
    __syncthreads();

    // per-lane A base addresses (read A fragments directly from staging)
    uint32_t addrA[2];
#pragma unroll
    for (int m2 = 0; m2 < 2; ++m2) {
        const int arow = (l & 7) | (((l >> 3) & 1) << 3);
        const int R = (2 * w + m2) * 16 + arow;
        const int Q = 4 * (R >> 4) + ((R >> 1) & 3);
        const int u = R & 1, v = (R >> 3) & 1;
        const int r = 2 * (Q >> 5) + u;
        const int c = 2 * (Q & 31) + v;
        addrA[m2] = sb + SM_SHI + (uint32_t)((r * CW + c) * 32) + (uint32_t)((l >> 4) * 16);
    }

    // epilogue lane constants
    const int a_ = l >> 2;
    const bool lead = (a_ & 1) == 0;
    const int jq = a_ >> 1;
    const int q0 = 2 * (l & 3);
    const int ue = a_ & 1;

    // two nt-half passes: acc = 32 regs per pass -> no spills under 128-reg cap
#pragma unroll 1
    for (int nh = 0; nh < 2; ++nh) {
        float acc[2][4][4];
#pragma unroll
        for (int a = 0; a < 2; ++a)
#pragma unroll
            for (int nt = 0; nt < 4; ++nt)
#pragma unroll
                for (int q = 0; q < 4; ++q) acc[a][nt][q] = 0.f;

#pragma unroll
        for (int s = 0; s < 9; ++s) {
            const uint32_t aoffs = (uint32_t)(((s / 3) * CW + (s % 3)) * 32);
            uint32_t A[2][4];
#pragma unroll
            for (int m2 = 0; m2 < 2; ++m2)
                ldsm_x4(A[m2][0], A[m2][1], A[m2][2], A[m2][3], addrA[m2] + aoffs);
            uint32_t bf[4][2];
            const uint32_t bbase = sb + SM_B + ((uint32_t)s * 16u + (uint32_t)(l & 15)) * 144u;
#pragma unroll
            for (int ntp = 0; ntp < 2; ++ntp)
                ldsm_x4_t(bf[2 * ntp][0], bf[2 * ntp][1], bf[2 * ntp + 1][0], bf[2 * ntp + 1][1],
                          bbase + (uint32_t)(nh * 4 + 2 * ntp + (l >> 4)) * 16u);
#pragma unroll
            for (int nt = 0; nt < 4; ++nt)
#pragma unroll
                for (int m2 = 0; m2 < 2; ++m2) {
                    float* c = acc[m2][nt];
                    mma16816(c[0], c[1], c[2], c[3],
                             A[m2][0], A[m2][1], A[m2][2], A[m2][3], bf[nt][0], bf[nt][1]);
                }
        }

        // epilogue for this nt-half: BN affine + certified interval pooling
#pragma unroll
        for (int m2 = 0; m2 < 2; ++m2) {
            const int mt = 2 * w + m2;
            const int Qq = 4 * mt + jq;
            const int rA = 2 * (Qq >> 5) + ue;
            const int cA = 2 * (Qq & 31);
            const float xnA = sXN[rA * 64 + cA];
            const float xnB = sXN[rA * 64 + cA + 1];
#pragma unroll
            for (int nt = 0; nt < 4; ++nt) {
                const int oc0 = (nh * 4 + nt) * 8 + q0, oc1 = oc0 + 1;
                const float* c = acc[m2][nt];
                float z0 = fmaf(c[0], sBN[oc0], sBN[64 + oc0]);
                float z1 = fmaf(c[1], sBN[oc1], sBN[64 + oc1]);
                float z2 = fmaf(c[2], sBN[oc0], sBN[64 + oc0]);
                float z3 = fmaf(c[3], sBN[oc1], sBN[64 + oc1]);
                const float K0 = sBN[128 + oc0], K1 = sBN[128 + oc1];
                float lo0 = fmaxf(z0 - K0 * xnA, z2 - K0 * xnB);
                float hi0 = fmaxf(z0 + K0 * xnA, z2 + K0 * xnB);
                float lo1 = fmaxf(z1 - K1 * xnA, z3 - K1 * xnB);
                float hi1 = fmaxf(z1 + K1 * xnA, z3 + K1 * xnB);
                lo0 = fmaxf(lo0, __shfl_xor_sync(0xffffffffu, lo0, 4));
                hi0 = fmaxf(hi0, __shfl_xor_sync(0xffffffffu, hi0, 4));
                lo1 = fmaxf(lo1, __shfl_xor_sync(0xffffffffu, lo1, 4));
                hi1 = fmaxf(hi1, __shfl_xor_sync(0xffffffffu, hi1, 4));
                if (lead) {
                    bool sp0 = lo0 > 1.0f;
                    spk[Qq * 64 + oc0] = sp0;
                    if (!sp0 && hi0 > 1.0f) {
                        int idx = atomicAdd(&sLC[0], 1);
                        sList[idx] = (uint16_t)(Qq * 64 + oc0);
                    }
                    bool sp1 = lo1 > 1.0f;
                    spk[Qq * 64 + oc1] = sp1;
                    if (!sp1 && hi1 > 1.0f) {
                        int idx = atomicAdd(&sLC[0], 1);
                        sList[idx] = (uint16_t)(Qq * 64 + oc1);
                    }
                }
            }
        }
    }
    __syncthreads();

    // in-block exact fixup of ambiguous windows (fp32 from smem)
    {
        const int cnt = sLC[0];
        for (int i = tid; i < cnt; i += 256) {
            const int e = sList[i];
            const int oc = e & 63, Q = e >> 6;
            const int r0 = 2 * (Q >> 5), c0 = 2 * (Q & 31);
            float a0 = 0.f, a1 = 0.f, a2 = 0.f, a3 = 0.f;
#pragma unroll 1
            for (int ic = 0; ic < IC1; ++ic) {
                float v[4][4];
#pragma unroll
                for (int iy = 0; iy < 4; ++iy)
#pragma unroll
                    for (int ix = 0; ix < 4; ++ix)
                        v[iy][ix] = sXF[((r0 + iy) * 66 + (c0 + ix)) * 10 + ic];
                const float* wr = w1 + oc * 90 + ic * 9;
#pragma unroll
                for (int ky = 0; ky < 3; ++ky)
#pragma unroll
                    for (int kx = 0; kx < 3; ++kx) {
                        float wv = __ldg(&wr[ky * 3 + kx]);
                        a0 = fmaf(wv, v[ky][kx],         a0);
                        a1 = fmaf(wv, v[ky][kx + 1],     a1);
                        a2 = fmaf(wv, v[ky + 1][kx],     a2);
                        a3 = fmaf(wv, v[ky + 1][kx + 1], a3);
                    }
            }
            const float inv = sBN[oc], bet = sBN[64 + oc];
            float zm = fmaxf(fmaxf(fmaf(a0, inv, bet), fmaf(a1, inv, bet)),
                             fmaxf(fmaf(a2, inv, bet), fmaf(a3, inv, bet)));
            spk[e] = (zm > 1.0f);
        }
    }
    __syncthreads();

    // reduce spike map -> aggregates
    {
        const int oc = tid & 63, grp = tid >> 6;
        int s = 0;
#pragma unroll
        for (int q = 0; q < 16; ++q) s += spk[(grp * 16 + q) * 64 + oc];
        sred[grp * 64 + oc] = s;
    }
    __syncthreads();
    if (tid < 64) {
        const int oc = tid;
        int Sf = sred[oc] + sred[64 + oc];          // quads 0-31 (pooled row 2by)
        int Sl = sred[128 + oc] + sred[192 + oc];   // quads 32-63 (pooled row 2by+1)
        int S = Sf + Sl;
        if (S) atomicAdd(&g_cnt[n][oc][0], S);
        if (by == 0 && Sf)  atomicAdd(&g_cnt[n][oc][1], Sf);
        if (by == 63 && Sl) atomicAdd(&g_cnt[n][oc][2], Sl);
        if (bx == 0) {
            int Cf = spk[0 * 64 + oc] + spk[32 * 64 + oc];
            if (Cf) atomicAdd(&g_cnt[n][oc][3], Cf);
            if (by == 0 && spk[0 * 64 + oc])   g_cnt[n][oc][5] = 1;
            if (by == 63 && spk[32 * 64 + oc]) g_cnt[n][oc][7] = 1;
        }
        if (bx == 3) {
            int Cl = spk[31 * 64 + oc] + spk[63 * 64 + oc];
            if (Cl) atomicAdd(&g_cnt[n][oc][4], Cl);
            if (by == 0 && spk[31 * 64 + oc])  g_cnt[n][oc][6] = 1;
            if (by == 63 && spk[63 * 64 + oc]) g_cnt[n][oc][8] = 1;
        }
    }
}

// ---------------------------------------------------------------------------
// stage B: analytic conv2-mean via T aggregates, BN2, spike -> g_s2
// ---------------------------------------------------------------------------
__global__ __launch_bounds__(256) void stageB_kernel(const float* __restrict__ w2) {
    __shared__ __align__(16) float sT[OC1 * 9];
    const int n = blockIdx.x, tid = threadIdx.x;
    const int lane = tid & 31, warp = tid >> 5;
    if (tid < OC1) {
        const int* c = g_cnt[n][tid];
        int S = c[0], Rf = c[1], Rl = c[2], Cf = c[3], Cl = c[4];
        int Re[3] = {Rl, 0, Rf};
        int Ce[3] = {Cl, 0, Cf};
        int Q[9]  = {c[8], 0, c[7],  0, 0, 0,  c[6], 0, c[5]};
#pragma unroll
        for (int k = 0; k < 9; ++k)
            sT[tid * 9 + k] = (float)(S - Re[k / 3] - Ce[k % 3] + Q[k]);
    }
    __syncthreads();
#pragma unroll 1
    for (int i = 0; i < 16; ++i) {
        const int o = warp * 16 + i;
        const float* wr = w2 + o * 576;
        float acc = 0.f;
#pragma unroll
        for (int t = 0; t < 18; ++t) {
            int j = t * 32 + lane;
            acc = fmaf(__ldg(&wr[j]), sT[j], acc);
        }
#pragma unroll
        for (int s = 16; s; s >>= 1) acc += __shfl_xor_sync(0xffffffffu, acc, s);
        if (lane == 0) {
            float z = acc * (1.f / 16384.f);
            z = z * g_inv2[o] + g_beta2[o];
            g_s2[n][o] = (z > 1.f) ? 1.f : 0.f;
        }
    }
}

// ---------------------------------------------------------------------------
// stage C: feat = |s0 - s1|, fc1+relu, fc2  -> out (32,5)
// ---------------------------------------------------------------------------
__global__ __launch_bounds__(256) void stageC_kernel(const float* __restrict__ fc1w,
                                                     const float* __restrict__ fc1b,
                                                     const float* __restrict__ fc2w,
                                                     const float* __restrict__ fc2b,
                                                     float* __restrict__ out) {
    __shared__ float f[128];
    __shared__ float h[64];
    const int n = blockIdx.x, tid = threadIdx.x;
    const int lane = tid & 31, warp = tid >> 5;
    if (tid < 128) f[tid] = fabsf(g_s2[n][tid] - g_s2[n + 32][tid]);
    __syncthreads();
#pragma unroll 1
    for (int i = 0; i < 8; ++i) {
        const int k = warp * 8 + i;
        const float* wr = fc1w + k * 128;
        float acc = 0.f;
#pragma unroll
        for (int t = 0; t < 4; ++t) {
            int j = t * 32 + lane;
            acc = fmaf(__ldg(&wr[j]), f[j], acc);
        }
#pragma unroll
        for (int s = 16; s; s >>= 1) acc += __shfl_xor_sync(0xffffffffu, acc, s);
        if (lane == 0) h[k] = fmaxf(acc + fc1b[k], 0.f);
    }
    __syncthreads();
    if (warp == 0) {
#pragma unroll 1
        for (int c = 0; c < 5; ++c) {
            const float* wr = fc2w + c * 64;
            float acc = fmaf(__ldg(&wr[lane]), h[lane], 0.f);
            acc = fmaf(__ldg(&wr[lane + 32]), h[lane + 32], acc);
#pragma unroll
            for (int s = 16; s; s >>= 1) acc += __shfl_xor_sync(0xffffffffu, acc, s);
            if (lane == 0) out[n * 5 + c] = acc + fc2b[c];
        }
    }
}

extern "C" void kernel_launch(void* const* d_in, const int* in_sizes, int n_in,
                              void* d_out, int out_size) {
    const float* x0   = (const float*)d_in[0];
    const float* x1   = (const float*)d_in[1];
    const float* w1   = (const float*)d_in[2];
    const float* b1g  = (const float*)d_in[3];
    const float* b1b  = (const float*)d_in[4];
    const float* b1m  = (const float*)d_in[5];
    const float* b1v  = (const float*)d_in[6];
    const float* w2   = (const float*)d_in[7];
    const float* b2g  = (const float*)d_in[8];
    const float* b2b  = (const float*)d_in[9];
    const float* b2m  = (const float*)d_in[10];
    const float* b2v  = (const float*)d_in[11];
    const float* fc1w = (const float*)d_in[12];
    const float* fc1b = (const float*)d_in[13];
    const float* fc2w = (const float*)d_in[14];
    const float* fc2b = (const float*)d_in[15];

    cudaFuncSetAttribute(stageT_kernel,
                         cudaFuncAttributeMaxDynamicSharedMemorySize, SMEM_BYTES);

    prep_kernel<<<64, 256>>>(w1, b1g, b1b, b1m, b1v, b2g, b2b, b2m, b2v);
    dim3 gridT(4, 64, 64);
    stageT_kernel<<<gridT, 256, SMEM_BYTES>>>(x0, x1, w1);
    stageB_kernel<<<64, 256>>>(w2);
    stageC_kernel<<<32, 256>>>(fc1w, fc1b, fc2w, fc2b, (float*)d_out);
}

// round 11
// speedup vs baseline: 1.1516x; 1.0907x over previous
#include <cuda_runtime.h>
#include <cstdint>

#define IC1 10
#define OC1 64
#define OC2 128
#define NB  64          // 2 images x 32 batch

__device__ int   g_cnt[NB][OC1][9];    // S, Rf, Rl, Cf, Cl, q_tl, q_tr, q_bl, q_br
__device__ float g_s2[NB][OC2];
__device__ float g_inv1[OC1],  g_beta1[OC1];
__device__ float g_inv2[OC2],  g_beta2[OC2];
__device__ float g_U[OC1][IC1][16];    // Winograd F(2x2,3x3) transformed weights

// packed fp32x2 (FFMA2) helpers
#define FMA_X2(d, a, b, c) \
    asm("fma.rn.f32x2 %0, %1, %2, %3;" : "=l"(d) : "l"(a), "l"(b), "l"(c))
#define PACK2(d, lo, hi) \
    asm("mov.b64 %0, {%1, %2};" : "=l"(d) : "r"(__float_as_uint(lo)), "r"(__float_as_uint(hi)))
#define UNPACK2(lo, hi, v) \
    asm("mov.b64 {%0, %1}, %2;" : "=r"(lo), "=r"(hi) : "l"(v))

// dynamic shared layout (floats)
#define SMF_U    0         // 64*10*16 = 10240 floats
#define SMF_IN   10240     // 10*34*34 = 11560 floats
#define SMF_SC   21800     // int[5][64] = 320 slots
#define SM_FLOATS 22120
#define SM_BYTES  (SM_FLOATS * 4)   // 88480 B -> 1 block/SM

// ---------------------------------------------------------------------------
// prep: zero counters, fold BN params, Winograd weight transform
// ---------------------------------------------------------------------------
__global__ void prep_kernel(const float* __restrict__ w1,
                            const float* __restrict__ g1, const float* __restrict__ b1,
                            const float* __restrict__ m1, const float* __restrict__ v1,
                            const float* __restrict__ g2, const float* __restrict__ b2,
                            const float* __restrict__ m2, const float* __restrict__ v2) {
    int gid = blockIdx.x * blockDim.x + threadIdx.x;
    int* c = &g_cnt[0][0][0];
    for (int i = gid; i < NB * OC1 * 9; i += gridDim.x * blockDim.x) c[i] = 0;
    if (blockIdx.x == 0) {
        int t = threadIdx.x;
        if (t < OC1) {
            float inv = g1[t] / sqrtf(v1[t] + 1e-5f);
            g_inv1[t] = inv;
            g_beta1[t] = b1[t] - m1[t] * inv;
        }
        if (t < OC2) {
            float inv = g2[t] / sqrtf(v2[t] + 1e-5f);
            g_inv2[t] = inv;
            g_beta2[t] = b2[t] - m2[t] * inv;
        }
    }
    if (gid < OC1 * IC1) {
        int oc = gid / IC1, ic = gid % IC1;
        const float* g = w1 + (oc * IC1 + ic) * 9;
        float gg[4][3];
#pragma unroll
        for (int cix = 0; cix < 3; ++cix) {
            float a = g[cix], b = g[3 + cix], d = g[6 + cix];
            gg[0][cix] = a;
            gg[1][cix] = 0.5f * (a + b + d);
            gg[2][cix] = 0.5f * (a - b + d);
            gg[3][cix] = d;
        }
        float* U = &g_U[oc][ic][0];
#pragma unroll
        for (int r = 0; r < 4; ++r) {
            float a = gg[r][0], b = gg[r][1], d = gg[r][2];
            U[r * 4 + 0] = a;
            U[r * 4 + 1] = 0.5f * (a + b + d);
            U[r * 4 + 2] = 0.5f * (a - b + d);
            U[r * 4 + 3] = d;
        }
    }
}

// ---------------------------------------------------------------------------
// stage A: Winograd conv1 (V in registers, FFMA2 over j-pairs, 255-reg budget)
//          + BN + maxpool2 + spike + 9-aggregate reduction
// grid (8, 8, 64), block 256, 1 block/SM. Thread = one pooled output (= one
// F(2x2,3x3) tile) for all 64 output channels. 16x16 pooled region per block.
// ---------------------------------------------------------------------------
__global__ __launch_bounds__(256, 1) void stageA_kernel(const float* __restrict__ x0,
                                                        const float* __restrict__ x1) {
    extern __shared__ float smem[];
    float* sU  = &smem[SMF_U];
    float* sin_ = &smem[SMF_IN];
    int*   sc  = (int*)&smem[SMF_SC];

    const int tid = threadIdx.x;
    const int bx = blockIdx.x, by = blockIdx.y, n = blockIdx.z;
    const float* __restrict__ x = (n < 32) ? x0 : x1;
    const int b = n & 31;

    // load all U: 10240 floats = 2560 float4
    {
        const float4* gU4 = (const float4*)&g_U[0][0][0];
        float4* sU4 = (float4*)sU;
        for (int i = tid; i < 2560; i += 256) sU4[i] = __ldg(&gU4[i]);
    }
    for (int i = tid; i < 5 * OC1; i += 256) sc[i] = 0;

    const int tx = tid & 15, ty = tid >> 4;
    const int gpy = by * 16 + ty, gpx = bx * 16 + tx;
    const int lane = tid & 31;
    const bool edge = (by == 0) | (by == 7) | (bx == 0) | (bx == 7);
    const int rr = 2 * ty, cc = 2 * tx;
    const int iy0 = by * 32 - 1;
    const int ix0 = bx * 32 - 1;

    // ---- phase 1a: stage ALL input channels at once (one barrier, high MLP) ----
    for (int i = tid; i < IC1 * 34 * 34; i += 256) {
        int ic = i / 1156, rem = i % 1156;
        int rw = rem / 34, cl = rem % 34;
        int gy = iy0 + rw, gx = ix0 + cl;
        float v = 0.f;
        if ((unsigned)gy < 256u && (unsigned)gx < 256u)
            v = __ldg(&x[((b * IC1 + ic) * 256 + gy) * 256 + gx]);
        sin_[i] = v;
    }
    __syncthreads();

    // ---- phase 1b: input transform -> V registers (no barriers) ----
    unsigned long long Vp[IC1][8];   // j-pairs: (j, j+1) for even j
#pragma unroll
    for (int ic = 0; ic < IC1; ++ic) {
        float d[4][4];
#pragma unroll
        for (int i = 0; i < 4; ++i) {
            const float2* p = (const float2*)&sin_[ic * 1156 + (rr + i) * 34 + cc];
            float2 u = p[0], w = p[1];
            d[i][0] = u.x; d[i][1] = u.y; d[i][2] = w.x; d[i][3] = w.y;
        }
        float t[4][4];
#pragma unroll
        for (int cix = 0; cix < 4; ++cix) {
            t[0][cix] = d[0][cix] - d[2][cix];
            t[1][cix] = d[1][cix] + d[2][cix];
            t[2][cix] = d[2][cix] - d[1][cix];
            t[3][cix] = d[1][cix] - d[3][cix];
        }
#pragma unroll
        for (int r = 0; r < 4; ++r) {
            float v0 = t[r][0] - t[r][2];
            float v1 = t[r][1] + t[r][2];
            float v2 = t[r][2] - t[r][1];
            float v3 = t[r][1] - t[r][3];
            PACK2(Vp[ic][r * 2 + 0], v0, v1);
            PACK2(Vp[ic][r * 2 + 1], v2, v3);
        }
    }

    // ---- phase 2: per-oc FFMA2 accumulate + output transform + epilogue ----
#pragma unroll 1
    for (int oc = 0; oc < OC1; ++oc) {
        const ulonglong2* up = (const ulonglong2*)&sU[oc * IC1 * 16];
        unsigned long long M[8];
#pragma unroll
        for (int j = 0; j < 8; ++j) M[j] = 0ULL;

#pragma unroll
        for (int ic = 0; ic < IC1; ++ic) {
            ulonglong2 ua  = up[ic * 4 + 0];
            ulonglong2 ub  = up[ic * 4 + 1];
            ulonglong2 uc2 = up[ic * 4 + 2];
            ulonglong2 ud  = up[ic * 4 + 3];
            FMA_X2(M[0], ua.x,  Vp[ic][0], M[0]);
            FMA_X2(M[1], ua.y,  Vp[ic][1], M[1]);
            FMA_X2(M[2], ub.x,  Vp[ic][2], M[2]);
            FMA_X2(M[3], ub.y,  Vp[ic][3], M[3]);
            FMA_X2(M[4], uc2.x, Vp[ic][4], M[4]);
            FMA_X2(M[5], uc2.y, Vp[ic][5], M[5]);
            FMA_X2(M[6], ud.x,  Vp[ic][6], M[6]);
            FMA_X2(M[7], ud.y,  Vp[ic][7], M[7]);
        }
        float m[16];
#pragma unroll
        for (int j = 0; j < 8; ++j) {
            unsigned lo, hi;
            UNPACK2(lo, hi, M[j]);
            m[2 * j]     = __uint_as_float(lo);
            m[2 * j + 1] = __uint_as_float(hi);
        }
        // output transform Y = A^T M A
        float q0[4], q1[4];
#pragma unroll
        for (int cix = 0; cix < 4; ++cix) {
            q0[cix] = m[cix] + m[4 + cix] + m[8 + cix];
            q1[cix] = m[4 + cix] - m[8 + cix] - m[12 + cix];
        }
        float y00 = q0[0] + q0[1] + q0[2];
        float y01 = q0[1] - q0[2] - q0[3];
        float y10 = q1[0] + q1[1] + q1[2];
        float y11 = q1[1] - q1[2] - q1[3];

        float inv = __ldg(&g_inv1[oc]);
        float bet = __ldg(&g_beta1[oc]);
        float mx = fmaxf(fmaxf(y00, y01), fmaxf(y10, y11));
        float mn = fminf(fminf(y00, y01), fminf(y10, y11));
        float z = (inv >= 0.f ? mx : mn) * inv + bet;
        bool sp = z > 1.0f;
        unsigned bal = __ballot_sync(0xffffffffu, sp);
        if (lane == 0 && bal) atomicAdd(&sc[0 * OC1 + oc], __popc(bal));
        if (edge) {
            unsigned bR0 = __ballot_sync(0xffffffffu, sp && (gpy == 0));
            unsigned bR1 = __ballot_sync(0xffffffffu, sp && (gpy == 127));
            unsigned bC0 = __ballot_sync(0xffffffffu, sp && (gpx == 0));
            unsigned bC1 = __ballot_sync(0xffffffffu, sp && (gpx == 127));
            if (lane == 0) {
                if (bR0) atomicAdd(&sc[1 * OC1 + oc], __popc(bR0));
                if (bR1) atomicAdd(&sc[2 * OC1 + oc], __popc(bR1));
                if (bC0) atomicAdd(&sc[3 * OC1 + oc], __popc(bC0));
                if (bC1) atomicAdd(&sc[4 * OC1 + oc], __popc(bC1));
            }
            if (sp) {  // corner bits (unique writer per corner; pre-zeroed)
                if (gpy == 0   && gpx == 0)        g_cnt[n][oc][5] = 1;
                else if (gpy == 0   && gpx == 127) g_cnt[n][oc][6] = 1;
                else if (gpy == 127 && gpx == 0)   g_cnt[n][oc][7] = 1;
                else if (gpy == 127 && gpx == 127) g_cnt[n][oc][8] = 1;
            }
        }
    }
    __syncthreads();
    if (tid < OC1) {
#pragma unroll
        for (int j = 0; j < 5; ++j) {
            int v = sc[j * OC1 + tid];
            if (v) atomicAdd(&g_cnt[n][tid][j], v);
        }
    }
}

// ---------------------------------------------------------------------------
// stage B: analytic conv2-mean via T aggregates, BN2, spike -> g_s2
// ---------------------------------------------------------------------------
__global__ __launch_bounds__(256) void stageB_kernel(const float* __restrict__ w2) {
    __shared__ __align__(16) float sT[OC1 * 9];
    const int n = blockIdx.x, tid = threadIdx.x;
    const int lane = tid & 31, warp = tid >> 5;
    if (tid < OC1) {
        const int* c = g_cnt[n][tid];
        int S = c[0], Rf = c[1], Rl = c[2], Cf = c[3], Cl = c[4];
        int Re[3] = {Rl, 0, Rf};
        int Ce[3] = {Cl, 0, Cf};
        int Q[9]  = {c[8], 0, c[7],  0, 0, 0,  c[6], 0, c[5]};
#pragma unroll
        for (int k = 0; k < 9; ++k)
            sT[tid * 9 + k] = (float)(S - Re[k / 3] - Ce[k % 3] + Q[k]);
    }
    __syncthreads();
#pragma unroll 1
    for (int i = 0; i < 16; ++i) {
        const int o = warp * 16 + i;
        const float* wr = w2 + o * 576;
        float acc = 0.f;
#pragma unroll
        for (int t = 0; t < 18; ++t) {
            int j = t * 32 + lane;
            acc = fmaf(__ldg(&wr[j]), sT[j], acc);
        }
#pragma unroll
        for (int s = 16; s; s >>= 1) acc += __shfl_xor_sync(0xffffffffu, acc, s);
        if (lane == 0) {
            float z = acc * (1.f / 16384.f);
            z = z * g_inv2[o] + g_beta2[o];
            g_s2[n][o] = (z > 1.f) ? 1.f : 0.f;
        }
    }
}

// ---------------------------------------------------------------------------
// stage C: feat = |s0 - s1|, fc1+relu, fc2  -> out (32,5)
// ---------------------------------------------------------------------------
__global__ __launch_bounds__(256) void stageC_kernel(const float* __restrict__ fc1w,
                                                     const float* __restrict__ fc1b,
                                                     const float* __restrict__ fc2w,
                                                     const float* __restrict__ fc2b,
                                                     float* __restrict__ out) {
    __shared__ float f[128];
    __shared__ float h[64];
    const int n = blockIdx.x, tid = threadIdx.x;
    const int lane = tid & 31, warp = tid >> 5;
    if (tid < 128) f[tid] = fabsf(g_s2[n][tid] - g_s2[n + 32][tid]);
    __syncthreads();
#pragma unroll 1
    for (int i = 0; i < 8; ++i) {
        const int k = warp * 8 + i;
        const float* wr = fc1w + k * 128;
        float acc = 0.f;
#pragma unroll
        for (int t = 0; t < 4; ++t) {
            int j = t * 32 + lane;
            acc = fmaf(__ldg(&wr[j]), f[j], acc);
        }
#pragma unroll
        for (int s = 16; s; s >>= 1) acc += __shfl_xor_sync(0xffffffffu, acc, s);
        if (lane == 0) h[k] = fmaxf(acc + fc1b[k], 0.f);
    }
    __syncthreads();
    if (warp == 0) {
#pragma unroll 1
        for (int c = 0; c < 5; ++c) {
            const float* wr = fc2w + c * 64;
            float acc = fmaf(__ldg(&wr[lane]), h[lane], 0.f);
            acc = fmaf(__ldg(&wr[lane + 32]), h[lane + 32], acc);
#pragma unroll
            for (int s = 16; s; s >>= 1) acc += __shfl_xor_sync(0xffffffffu, acc, s);
            if (lane == 0) out[n * 5 + c] = acc + fc2b[c];
        }
    }
}

extern "C" void kernel_launch(void* const* d_in, const int* in_sizes, int n_in,
                              void* d_out, int out_size) {
    const float* x0   = (const float*)d_in[0];
    const float* x1   = (const float*)d_in[1];
    const float* w1   = (const float*)d_in[2];
    const float* b1g  = (const float*)d_in[3];
    const float* b1b  = (const float*)d_in[4];
    const float* b1m  = (const float*)d_in[5];
    const float* b1v  = (const float*)d_in[6];
    const float* w2   = (const float*)d_in[7];
    const float* b2g  = (const float*)d_in[8];
    const float* b2b  = (const float*)d_in[9];
    const float* b2m  = (const float*)d_in[10];
    const float* b2v  = (const float*)d_in[11];
    const float* fc1w = (const float*)d_in[12];
    const float* fc1b = (const float*)d_in[13];
    const float* fc2w = (const float*)d_in[14];
    const float* fc2b = (const float*)d_in[15];

    cudaFuncSetAttribute(stageA_kernel,
                         cudaFuncAttributeMaxDynamicSharedMemorySize, SM_BYTES);

    prep_kernel<<<32, 256>>>(w1, b1g, b1b, b1m, b1v, b2g, b2b, b2m, b2v);
    dim3 gridA(8, 8, 64);
    stageA_kernel<<<gridA, 256, SM_BYTES>>>(x0, x1);
    stageB_kernel<<<64, 256>>>(w2);
    stageC_kernel<<<32, 256>>>(fc1w, fc1b, fc2w, fc2b, (float*)d_out);
}